// round 11
// baseline (speedup 1.0000x reference)
#include <cuda_runtime.h>

#define L_Q   1024
#define B_Q   64
#define D_Q   512
#define U_Q   20
#define LTOT  3072                 // 3*L
#define NFRAG 7
#define FLEN  439                  // ceil(3072/7); 7*439 = 3073, pad = 1
#define NCH   (NFRAG * B_Q)        // 448 independent scan chains
#define SCAN_CHB 8                 // chains per scan block (static smem 28.2 KB)

// GEMM: split-K x2, 1 row/thread, coalesced swizzled staging.
// 512 blocks x 256 threads (8 warps). Warp w: rowgrp=w>>1 (32 rows),
// khalf=w&1 (k in [khalf*256, khalf*256+256)). 4096 warps chip-wide.
#define KH    256                  // k per half
#define KC    32                   // k per chunk (128B per row)
#define NCW   (KH / KC)            // 8 chunks per warp
#define WBUF  (2 * 32 * KC)        // floats per warp double buffer = 2048 (8KB)
#define W_FL  (D_Q * U_Q)          // 10240 floats
#define GEMM_SMEM ((W_FL + 8 * WBUF) * 4)    // 106496 B -> 2 blocks/SM

// Scratch (no allocations allowed -> __device__ globals)
__device__ float2 g_c2[FLEN * NCH];                      // (c1, c2) per step, [ls][chain]
__device__ float  g_coords[(NFRAG * FLEN) * B_Q * 3];    // raw fragment coords [(f*FLEN+l)][b][3]
__device__ float4 g_Mt4[NFRAG * B_Q * 3];                // per (frag,b): [M00 M01 M02 M10][M11 M12 M20 M21][M22 tx ty tz]

static __device__ __forceinline__ unsigned smem_u32(const void* p) {
    return (unsigned)__cvta_generic_to_shared(p);
}
static __device__ __forceinline__ void cp16(unsigned dst, const void* src) {
    asm volatile("cp.async.cg.shared.global [%0], [%1], 16;"
                 :: "r"(dst), "l"(src) : "memory");
}

// =====================================================================
// Kernel 1: logits GEMM (65536 x 512 x 20) + softmax-free angularization.
// KEY FIX vs R6-R10: each cp.async warp-instruction covers 4 rows x 128B
// CONTIGUOUS (4 full lines = 4 L1tex wavefronts, vs 32 before). Smem rows
// stored 128B-stride with XOR-8 swizzle (physical q = logical q ^ (row&7))
// so per-phase LDS.128 reads are conflict-free without padding.
// 1 row/thread + split-K x2 -> 4096 warps (6.9/SMSP at 2 blocks/SM) to
// saturate issue. Warp-private double-buffer pipelines, no block barriers
// in the mainloop. Pair reduction via smem; epilogue on khalf=0 warps.
// =====================================================================
__global__ __launch_bounds__(256, 2) void k_gemm(
    const float* __restrict__ inp, const float* __restrict__ W,
    const float* __restrict__ bias, const float* __restrict__ alpha,
    const float* __restrict__ bl, const float* __restrict__ ba)
{
    extern __shared__ float sm[];                        // [W_FL | 8 x WBUF]
    __shared__ float sSin[U_Q * 3], sCos[U_Q * 3], sB[U_Q];
    int tid = threadIdx.x;
    int w = tid >> 5, lane = tid & 31;
    int rowgrp = w >> 1, khalf = w & 1;

    // W transposed into smem: sW[k][u]
    for (int idx = tid; idx < W_FL; idx += 256) {
        int u = idx >> 9, k = idx & (D_Q - 1);
        sm[k * U_Q + u] = W[idx];
    }
    if (tid < U_Q * 3) { float a = alpha[tid]; sSin[tid] = sinf(a); sCos[tid] = cosf(a); }
    if (tid < U_Q) sB[tid] = bias[tid];

    // pNeRF pad element (global position 3072 -> frag 6, step ls=438):
    // its coordinate is dropped and its frame never consumed.
    if (blockIdx.x == 0 && tid < B_Q) {
        g_c2[(FLEN - 1) * NCH + 6 * B_Q + tid] = make_float2(0.1f, 0.1f);
    }

    float rs[3];
#pragma unroll
    for (int j = 0; j < 3; j++) rs[j] = bl[j] * sinf(ba[j]);

    int warpRow = blockIdx.x * 128 + rowgrp * 32;        // 32 rows per warp
    const float* gsrc = inp + (size_t)warpRow * D_Q + khalf * KH;
    float* mybuf = sm + W_FL + w * WBUF;
    unsigned myb0 = smem_u32(mybuf);

    // issue chunk c into warp-private half-buffer c&1:
    // 8 instructions; instr i: 4 rows x 128B contiguous (4 lines, 4 wf).
    // dst swizzle: physical 16B-slot = q ^ (row&7).
#define ISSUE(c)                                                              \
    {                                                                         \
        unsigned _b = myb0 + (unsigned)(((c) & 1) * (32 * KC)) * 4u;          \
        const float* _g = gsrc + (c) * KC;                                    \
        _Pragma("unroll")                                                     \
        for (int i = 0; i < 8; i++) {                                         \
            int _idx = i * 32 + lane;                                         \
            int _r = _idx >> 3, _q = _idx & 7;                                \
            cp16(_b + (unsigned)(_r * 128 + ((_q ^ (_r & 7)) << 4)),          \
                 _g + (size_t)_r * D_Q + _q * 4);                             \
        }                                                                     \
        asm volatile("cp.async.commit_group;" ::: "memory");                  \
    }

    ISSUE(0)
    ISSUE(1)
    __syncthreads();                                     // W / sSin ready
    asm volatile("cp.async.wait_group 1;" ::: "memory"); // chunk 0 done
    __syncwarp();

    float acc[U_Q];
#pragma unroll
    for (int u = 0; u < U_Q; u++) acc[u] = 0.f;

    int s = lane & 7;                                    // this row's swizzle key
#pragma unroll 1
    for (int c = 0; c < NCW; ++c) {
        const float4* arow = (const float4*)(mybuf + (c & 1) * (32 * KC) + lane * KC);
        const float* wk = sm + (khalf * KH + c * KC) * U_Q;
#pragma unroll
        for (int g = 0; g < 8; ++g) {
            float4 a4 = arow[g ^ s];                     // de-swizzle (conflict-free)
#pragma unroll
            for (int kk = 0; kk < 4; ++kk) {
                float wv[U_Q];
#pragma unroll
                for (int q = 0; q < 5; ++q)
                    *(float4*)(wv + q * 4) = ((const float4*)(wk + (g * 4 + kk) * U_Q))[q];
                float va = ((const float*)&a4)[kk];
#pragma unroll
                for (int u = 0; u < U_Q; u++)
                    acc[u] = fmaf(va, wv[u], acc[u]);
            }
        }
        __syncwarp();                                    // lanes done with buf c&1
        if (c + 2 < NCW) {
            ISSUE(c + 2)
            asm volatile("cp.async.wait_group 1;" ::: "memory"); // c+1 done
        } else {
            asm volatile("cp.async.wait_group 0;" ::: "memory");
        }
        __syncwarp();
    }
#undef ISSUE

    // ---- pair reduction: khalf=1 writes partials, khalf=0 adds ----
    float* spart = sm + W_FL;                            // reuse A region
    __syncthreads();
    if (khalf == 1) {
        float* p = spart + (rowgrp * 32 + lane) * U_Q;
#pragma unroll
        for (int u = 0; u < U_Q; u++) p[u] = acc[u];
    }
    __syncthreads();
    if (khalf == 1) return;

    {
        const float* p = spart + (rowgrp * 32 + lane) * U_Q;
#pragma unroll
        for (int u = 0; u < U_Q; u++) acc[u] += p[u];
    }

    {
        float* lg = acc;
        float mx = -1e30f;
#pragma unroll
        for (int u = 0; u < U_Q; u++) { lg[u] += sB[u]; mx = fmaxf(mx, lg[u]); }
        // softmax numerator only: cos/sin(phi) from (s,c) ratio; softmax
        // normalization cancels.
        float sj[3] = {0.f,0.f,0.f}, cj[3] = {0.f,0.f,0.f};
#pragma unroll
        for (int u = 0; u < U_Q; u++) {
            float e = __expf(lg[u] - mx);
#pragma unroll
            for (int j = 0; j < 3; j++) {
                sj[j] = fmaf(e, sSin[u*3+j], sj[j]);
                cj[j] = fmaf(e, sCos[u*3+j], cj[j]);
            }
        }
        int row = warpRow + lane;
        int l = row >> 6, b = row & 63;
#pragma unroll
        for (int j = 0; j < 3; j++) {
            float sv = sj[j], c2v = cj[j];
            float rn = rsqrtf(fmaf(sv, sv, c2v * c2v));
            int m  = 3 * l + j;
            int f  = m / FLEN;
            int ls = m - f * FLEN;
            g_c2[ls * NCH + f * B_Q + b] =
                make_float2(rs[j] * (c2v * rn), rs[j] * (sv * rn));
        }
    }
}

// =====================================================================
// Kernel 2: pNeRF scan; state (bc, N, sfac) with mh = sfac*(N x bc)
// folded in algebraically (stable Newton-corrected normalization).
//   G = N x bc;  Y = c1*G + c2*N;  d = sfac*Y + rc*bc
//   bc' = d/r (analytic);  N' = bc x d;  sfac' = nA - nB*|N'|^2
// =====================================================================
__global__ __launch_bounds__(64) void k_scan(const float* __restrict__ bl,
                                             const float* __restrict__ ba)
{
    __shared__ float2 sc[(FLEN + 2) * SCAN_CHB];         // 28.2 KB static
    int tid = threadIdx.x;
    int chain0 = blockIdx.x * SCAN_CHB;
    for (int idx = tid; idx < (FLEN + 2) * SCAN_CHB; idx += 64) {
        int lsr = idx >> 3;
        int lane = idx & 7;
        sc[idx] = (lsr < FLEN) ? g_c2[lsr * NCH + chain0 + lane]
                               : make_float2(0.f, 0.f);
    }
    __syncthreads();
    if (tid >= SCAN_CHB) return;
    int chain = chain0 + tid;
    int f = chain >> 6, b = chain & 63;
    int ph = f % 3;

    float rcA[3], irA[3], nA[3], nB[3];
#pragma unroll
    for (int k = 0; k < 3; k++) {
        int j = ph + k; if (j >= 3) j -= 3;
        float r = bl[j], t = ba[j];
        rcA[k] = r * cosf(t);
        irA[k] = 1.f / r;
        float x0 = 1.f / (r * sinf(t));
        nA[k] = 1.5f * x0;
        nB[k] = 0.5f * x0 * x0 * x0;
    }

    // init: bc=(1,0,0), n=(0,0,1) -> N=(0,0,1), sfac=1 (mh=(0,1,0) implied)
    float bcx = 1.f, bcy = 0.f, bcz = 0.f;
    float Nx  = 0.f, Ny  = 0.f, Nz  = 1.f;
    float sfac = 1.f;
    float Cx = 0.f, Cy = 0.f, Cz = 0.f;

    float* outp = &g_coords[(((size_t)f * FLEN) * B_Q + b) * 3];
    const float2* pp = sc + tid;
    float2 pa = pp[0];
    float2 pb = pp[SCAN_CHB];
    int l = 0;

#define SCAN_STEP(k)                                                         \
    {                                                                        \
        float2 cc = pa; pa = pb; pb = pp[(l + 2) * SCAN_CHB];                \
        float Gx = fmaf(Ny, bcz, -(Nz * bcy));                               \
        float Gy = fmaf(Nz, bcx, -(Nx * bcz));                               \
        float Gz = fmaf(Nx, bcy, -(Ny * bcx));                               \
        float Yx = fmaf(cc.x, Gx, cc.y * Nx);                                \
        float Yy = fmaf(cc.x, Gy, cc.y * Ny);                                \
        float Yz = fmaf(cc.x, Gz, cc.y * Nz);                                \
        float dx = fmaf(sfac, Yx, rcA[k] * bcx);                             \
        float dy = fmaf(sfac, Yy, rcA[k] * bcy);                             \
        float dz = fmaf(sfac, Yz, rcA[k] * bcz);                             \
        float N2x = fmaf(bcy, dz, -(bcz * dy));                              \
        float N2y = fmaf(bcz, dx, -(bcx * dz));                              \
        float N2z = fmaf(bcx, dy, -(bcy * dx));                              \
        bcx = dx * irA[k]; bcy = dy * irA[k]; bcz = dz * irA[k];             \
        float d2 = fmaf(N2x, N2x, fmaf(N2y, N2y, N2z * N2z));                \
        sfac = fmaf(d2, -nB[k], nA[k]);                                      \
        Nx = N2x; Ny = N2y; Nz = N2z;                                        \
        Cx += dx; Cy += dy; Cz += dz;                                        \
        float* o = outp + (size_t)l * (B_Q * 3);                             \
        o[0] = Cx; o[1] = Cy; o[2] = Cz;                                     \
        ++l;                                                                 \
    }

    for (int it = 0; it < 146; ++it) { SCAN_STEP(0) SCAN_STEP(1) SCAN_STEP(2) }
    SCAN_STEP(0)                                         // 439 = 3*146 + 1
#undef SCAN_STEP
}

// =====================================================================
// Kernel 3a: per-batch cumulative fragment transforms (composed affine).
// =====================================================================
__global__ void k_align()
{
    int b = threadIdx.x;
    if (b >= B_Q) return;
    float M00=1.f,M01=0.f,M02=0.f,M10=0.f,M11=1.f,M12=0.f,M20=0.f,M21=0.f,M22=1.f;
    float tx=0.f,ty=0.f,tz=0.f;
    {
        float4* mt = &g_Mt4[(size_t)b * 3];
        mt[0] = make_float4(1.f,0.f,0.f,0.f);
        mt[1] = make_float4(1.f,0.f,0.f,0.f);
        mt[2] = make_float4(1.f,0.f,0.f,0.f);
    }
    for (int j = 0; j < NFRAG - 1; ++j) {
        const float* A = &g_coords[(((size_t)j * FLEN + (FLEN - 3)) * B_Q + b) * 3];
        const float* Bv = A + B_Q * 3;
        const float* Cv = Bv + B_Q * 3;
        float bx=Cv[0]-Bv[0], by=Cv[1]-Bv[1], bz=Cv[2]-Bv[2];
        float ax=Bv[0]-A[0],  ay=Bv[1]-A[1],  az=Bv[2]-A[2];
        float Nx=fmaf(ay,bz,-az*by), Ny=fmaf(az,bx,-ax*bz), Nz=fmaf(ax,by,-ay*bx);
        float s1=rsqrtf(fmaf(bx,bx,fmaf(by,by,bz*bz)));
        float s2=rsqrtf(fmaf(Nx,Nx,fmaf(Ny,Ny,Nz*Nz)));
        float s12=s1*s2;
        float mxv=fmaf(Ny,bz,-Nz*by)*s12;
        float myv=fmaf(Nz,bx,-Nx*bz)*s12;
        float mzv=fmaf(Nx,by,-Ny*bx)*s12;
        float bcx=bx*s1, bcy=by*s1, bcz=bz*s1;
        float nx=Nx*s2,  ny=Ny*s2,  nz=Nz*s2;
        float N00 = M00*bcx + M01*bcy + M02*bcz;
        float N10 = M10*bcx + M11*bcy + M12*bcz;
        float N20 = M20*bcx + M21*bcy + M22*bcz;
        float N01 = M00*mxv + M01*myv + M02*mzv;
        float N11 = M10*mxv + M11*myv + M12*mzv;
        float N21 = M20*mxv + M21*myv + M22*mzv;
        float N02 = M00*nx + M01*ny + M02*nz;
        float N12 = M10*nx + M11*ny + M12*nz;
        float N22 = M20*nx + M21*ny + M22*nz;
        float ntx = tx + M00*Cv[0] + M01*Cv[1] + M02*Cv[2];
        float nty = ty + M10*Cv[0] + M11*Cv[1] + M12*Cv[2];
        float ntz = tz + M20*Cv[0] + M21*Cv[1] + M22*Cv[2];
        M00=N00;M01=N01;M02=N02;M10=N10;M11=N11;M12=N12;M20=N20;M21=N21;M22=N22;
        tx=ntx;ty=nty;tz=ntz;
        float4* mt = &g_Mt4[((size_t)(j + 1) * B_Q + b) * 3];
        mt[0] = make_float4(M00,M01,M02,M10);
        mt[1] = make_float4(M11,M12,M20,M21);
        mt[2] = make_float4(M22,tx,ty,tz);
    }
}

// =====================================================================
// Kernel 3b: apply per-fragment affine; b-pair per thread (float2 IO).
// =====================================================================
__global__ __launch_bounds__(256) void k_out(float* __restrict__ out)
{
    int t = blockIdx.x * 256 + threadIdx.x;              // t < 98304
    int m = t >> 5;
    int b0 = (t & 31) * 2;
    int f = m / FLEN;
    const float2* X = (const float2*)&g_coords[((size_t)m * B_Q + b0) * 3];
    float2 x0 = X[0], x1 = X[1], x2 = X[2];
    const float4* Ma = &g_Mt4[((size_t)f * B_Q + b0) * 3];
    float4 a0 = Ma[0], a1 = Ma[1], a2 = Ma[2];
    float4 b0v = Ma[3], b1v = Ma[4], b2v = Ma[5];
    float r0x = fmaf(a0.x, x0.x, fmaf(a0.y, x0.y, fmaf(a0.z, x1.x, a2.y)));
    float r0y = fmaf(a0.w, x0.x, fmaf(a1.x, x0.y, fmaf(a1.y, x1.x, a2.z)));
    float r0z = fmaf(a1.z, x0.x, fmaf(a1.w, x0.y, fmaf(a2.x, x1.x, a2.w)));
    float r1x = fmaf(b0v.x, x1.y, fmaf(b0v.y, x2.x, fmaf(b0v.z, x2.y, b2v.y)));
    float r1y = fmaf(b0v.w, x1.y, fmaf(b1v.x, x2.x, fmaf(b1v.y, x2.y, b2v.z)));
    float r1z = fmaf(b1v.z, x1.y, fmaf(b1v.w, x2.x, fmaf(b2v.x, x2.y, b2v.w)));
    float2* O = (float2*)(out + ((size_t)m * B_Q + b0) * 3);
    O[0] = make_float2(r0x, r0y);
    O[1] = make_float2(r0z, r1x);
    O[2] = make_float2(r1y, r1z);
}

extern "C" void kernel_launch(void* const* d_in, const int* in_sizes, int n_in,
                              void* d_out, int out_size)
{
    (void)in_sizes; (void)n_in; (void)out_size;
    const float* inp   = (const float*)d_in[0];
    const float* W     = (const float*)d_in[1];
    const float* bias  = (const float*)d_in[2];
    const float* alpha = (const float*)d_in[3];
    const float* bl    = (const float*)d_in[4];
    const float* ba    = (const float*)d_in[5];
    // d_in[6] = nfrag (== 7 by construction; compile-time constant here)

    static int attr_done = 0;
    if (!attr_done) {
        cudaFuncSetAttribute(k_gemm, cudaFuncAttributeMaxDynamicSharedMemorySize, GEMM_SMEM);
        attr_done = 1;
    }

    k_gemm <<<512, 256, GEMM_SMEM>>>(inp, W, bias, alpha, bl, ba);
    k_scan <<<NCH / SCAN_CHB, 64>>>(bl, ba);              // 56 blocks * 8 chains
    k_align<<<1, 64>>>();
    k_out  <<<384, 256>>>((float*)d_out);                 // b-pair float2 IO
}

// round 12
// speedup vs baseline: 1.1510x; 1.1510x over previous
#include <cuda_runtime.h>

#define L_Q   1024
#define B_Q   64
#define D_Q   512
#define U_Q   20
#define LTOT  3072                 // 3*L
#define NFRAG 7
#define FLEN  439                  // ceil(3072/7); 7*439 = 3073, pad = 1
#define NCH   (NFRAG * B_Q)        // 448 independent scan chains
#define SCAN_CHB 8                 // chains per scan block (static smem 28.2 KB)

// GEMM (tensor): warp = 32 rows x 24 u x K=512, mma.m16n8k8 tf32 split.
#define RPW   32                   // rows per warp
#define KC    16                   // k per staged chunk (64B per row)
#define NCHK  (D_Q / KC)           // 32 chunks
#define ROWW  20                   // words per staged row (16 data + 4 pad = 80B, odd-16B)
#define ABUF  (2 * RPW * ROWW)     // per-warp double buffer words = 1280
#define WPAD  24                   // u padded to 24 (3 n-tiles of 8)
#define WS_FL (D_Q * WPAD)         // 12288 words
#define GEMM_SMEM ((WS_FL + 8 * ABUF) * 4)   // 90112 B -> 2 blocks/SM

// Scratch (no allocations allowed -> __device__ globals)
__device__ float2 g_c2[FLEN * NCH];                      // (c1, c2) per step, [ls][chain]
__device__ float  g_coords[(NFRAG * FLEN) * B_Q * 3];    // raw fragment coords [(f*FLEN+l)][b][3]
__device__ float4 g_Mt4[NFRAG * B_Q * 3];                // per (frag,b): [M00 M01 M02 M10][M11 M12 M20 M21][M22 tx ty tz]

static __device__ __forceinline__ unsigned smem_u32(const void* p) {
    return (unsigned)__cvta_generic_to_shared(p);
}
static __device__ __forceinline__ void cp16(unsigned dst, const void* src) {
    asm volatile("cp.async.cg.shared.global [%0], [%1], 16;"
                 :: "r"(dst), "l"(src) : "memory");
}
static __device__ __forceinline__ unsigned f2tf32(float x) {
    unsigned r;
    asm("cvt.rna.tf32.f32 %0, %1;" : "=r"(r) : "f"(x));
    return r;
}
static __device__ __forceinline__ void mma_tf32(float* c, const unsigned* a,
                                                unsigned b0, unsigned b1) {
    asm volatile(
        "mma.sync.aligned.m16n8k8.row.col.f32.tf32.tf32.f32 "
        "{%0,%1,%2,%3}, {%4,%5,%6,%7}, {%8,%9}, {%0,%1,%2,%3};"
        : "+f"(c[0]), "+f"(c[1]), "+f"(c[2]), "+f"(c[3])
        : "r"(a[0]), "r"(a[1]), "r"(a[2]), "r"(a[3]), "r"(b0), "r"(b1));
}

// =====================================================================
// Kernel 1: logits GEMM (65536 x 512 x 20) via tf32-split tensor mma +
// softmax-free angularization.
// Breaks the scalar invariant (1 smem wavefront per warp-FFMA feeding W):
// operands flow through mma fragments. A = Ah+Al, W = Wh+Wl (tf32 hi +
// tf32 residual); AhWh + AlWh + AhWl. Warp owns 32 rows x 24 u x K=512
// (2 m-tiles x 3 n-tiles, no split-K -> no reduction). A staged fp32 in
// warp-private 80B-stride rows (odd 16B -> conflict-free per-lane frag
// loads); W fp32 in smem [k][24], converted per-fragment on the fly.
// 256 blocks x 256 thr = single wave; DRAM-bound (~16us floor).
// =====================================================================
__global__ __launch_bounds__(256, 2) void k_gemm(
    const float* __restrict__ inp, const float* __restrict__ W,
    const float* __restrict__ bias, const float* __restrict__ alpha,
    const float* __restrict__ bl, const float* __restrict__ ba)
{
    extern __shared__ float sm[];                        // [WS_FL | 8 x ABUF]
    __shared__ float sSin[U_Q * 3], sCos[U_Q * 3], sB[U_Q];
    int tid = threadIdx.x;
    int w = tid >> 5, lane = tid & 31;
    int g = lane >> 2, tg = lane & 3;

    // W into smem as sW[k][u'] (u' padded to 24 with zeros)
    for (int idx = tid; idx < WS_FL; idx += 256) {
        int k = idx / WPAD, u = idx - k * WPAD;
        sm[idx] = (u < U_Q) ? W[u * D_Q + k] : 0.f;
    }
    if (tid < U_Q * 3) { float a = alpha[tid]; sSin[tid] = sinf(a); sCos[tid] = cosf(a); }
    if (tid < U_Q) sB[tid] = bias[tid];

    // pNeRF pad element (global position 3072 -> frag 6, step ls=438):
    // its coordinate is dropped and its frame never consumed.
    if (blockIdx.x == 0 && tid < B_Q) {
        g_c2[(FLEN - 1) * NCH + 6 * B_Q + tid] = make_float2(0.1f, 0.1f);
    }

    float rs[3];
#pragma unroll
    for (int j = 0; j < 3; j++) rs[j] = bl[j] * sinf(ba[j]);

    int warpRow = blockIdx.x * 256 + w * RPW;
    const float* gsrc = inp + (size_t)warpRow * D_Q;
    float* mybuf = sm + WS_FL + w * ABUF;
    unsigned myb0 = smem_u32(mybuf);

    // stage chunk c (32 rows x 64B) into half-buffer c&1: 4 cp16/lane,
    // each instruction covers 8 rows x 64B contiguous.
#define ISSUE(c)                                                              \
    {                                                                         \
        unsigned _b = myb0 + (unsigned)(((c) & 1) * (RPW * ROWW)) * 4u;       \
        const float* _g = gsrc + (c) * KC;                                    \
        _Pragma("unroll")                                                     \
        for (int i = 0; i < 4; i++) {                                         \
            int _idx = i * 32 + lane;                                         \
            int _r = _idx >> 2, _q = _idx & 3;                                \
            cp16(_b + (unsigned)(_r * ROWW + _q * 4) * 4u,                    \
                 _g + (size_t)_r * D_Q + _q * 4);                             \
        }                                                                     \
        asm volatile("cp.async.commit_group;" ::: "memory");                  \
    }

    ISSUE(0)
    ISSUE(1)
    __syncthreads();                                     // W / sSin ready
    asm volatile("cp.async.wait_group 1;" ::: "memory"); // chunk 0 done
    __syncwarp();

    float acc[2][3][4];
#pragma unroll
    for (int mt = 0; mt < 2; mt++)
#pragma unroll
        for (int nt = 0; nt < 3; nt++)
#pragma unroll
            for (int i = 0; i < 4; i++) acc[mt][nt][i] = 0.f;

#pragma unroll 1
    for (int c = 0; c < NCHK; ++c) {
        const float* bufw = mybuf + (c & 1) * (RPW * ROWW);
#pragma unroll
        for (int kw = 0; kw < 2; ++kw) {                 // two k8 windows per chunk
            int kb = kw * 8;
            // A fragments (hi/lo) for 2 m-tiles
            unsigned ah[2][4], al[2][4];
#pragma unroll
            for (int mt = 0; mt < 2; mt++) {
                int r0 = mt * 16 + g, r1 = mt * 16 + 8 + g;
                float x0 = bufw[r0 * ROWW + kb + tg];
                float x1 = bufw[r1 * ROWW + kb + tg];
                float x2 = bufw[r0 * ROWW + kb + tg + 4];
                float x3 = bufw[r1 * ROWW + kb + tg + 4];
                ah[mt][0] = f2tf32(x0); al[mt][0] = f2tf32(x0 - __uint_as_float(ah[mt][0]));
                ah[mt][1] = f2tf32(x1); al[mt][1] = f2tf32(x1 - __uint_as_float(ah[mt][1]));
                ah[mt][2] = f2tf32(x2); al[mt][2] = f2tf32(x2 - __uint_as_float(ah[mt][2]));
                ah[mt][3] = f2tf32(x3); al[mt][3] = f2tf32(x3 - __uint_as_float(ah[mt][3]));
            }
            int k0 = c * KC + kb;
#pragma unroll
            for (int nt = 0; nt < 3; nt++) {
                float w0 = sm[(k0 + tg) * WPAD + nt * 8 + g];
                float w1 = sm[(k0 + tg + 4) * WPAD + nt * 8 + g];
                unsigned bh0 = f2tf32(w0), bl0 = f2tf32(w0 - __uint_as_float(bh0));
                unsigned bh1 = f2tf32(w1), bl1 = f2tf32(w1 - __uint_as_float(bh1));
#pragma unroll
                for (int mt = 0; mt < 2; mt++) {
                    mma_tf32(acc[mt][nt], ah[mt], bh0, bh1);   // Ah*Wh
                    mma_tf32(acc[mt][nt], al[mt], bh0, bh1);   // Al*Wh
                    mma_tf32(acc[mt][nt], ah[mt], bl0, bl1);   // Ah*Wl
                }
            }
        }
        __syncwarp();
        if (c + 2 < NCHK) {
            ISSUE(c + 2)
            asm volatile("cp.async.wait_group 1;" ::: "memory");
        } else {
            asm volatile("cp.async.wait_group 0;" ::: "memory");
        }
        __syncwarp();
    }
#undef ISSUE

    // ---- epilogue: fragments -> warp-private smem logits (stride 25) ----
    float* sL = mybuf;                                   // 1280 words >= 32*25
    __syncwarp();
#pragma unroll
    for (int mt = 0; mt < 2; mt++)
#pragma unroll
        for (int nt = 0; nt < 3; nt++) {
            int cbase = nt * 8 + tg * 2;
            sL[(mt * 16 + g) * 25 + cbase]         = acc[mt][nt][0];
            sL[(mt * 16 + g) * 25 + cbase + 1]     = acc[mt][nt][1];
            sL[(mt * 16 + g + 8) * 25 + cbase]     = acc[mt][nt][2];
            sL[(mt * 16 + g + 8) * 25 + cbase + 1] = acc[mt][nt][3];
        }
    __syncwarp();

    {
        float lg[U_Q];
        float mx = -1e30f;
#pragma unroll
        for (int u = 0; u < U_Q; u++) {
            lg[u] = sL[lane * 25 + u] + sB[u];
            mx = fmaxf(mx, lg[u]);
        }
        // softmax numerator only: cos/sin(phi) from (s,c) ratio; softmax
        // normalization cancels.
        float sj[3] = {0.f,0.f,0.f}, cj[3] = {0.f,0.f,0.f};
#pragma unroll
        for (int u = 0; u < U_Q; u++) {
            float e = __expf(lg[u] - mx);
#pragma unroll
            for (int j = 0; j < 3; j++) {
                sj[j] = fmaf(e, sSin[u*3+j], sj[j]);
                cj[j] = fmaf(e, sCos[u*3+j], cj[j]);
            }
        }
        int row = warpRow + lane;
        int l = row >> 6, b = row & 63;
#pragma unroll
        for (int j = 0; j < 3; j++) {
            float sv = sj[j], c2v = cj[j];
            float rn = rsqrtf(fmaf(sv, sv, c2v * c2v));
            int m  = 3 * l + j;
            int f  = m / FLEN;
            int ls = m - f * FLEN;
            g_c2[ls * NCH + f * B_Q + b] =
                make_float2(rs[j] * (c2v * rn), rs[j] * (sv * rn));
        }
    }
}

// =====================================================================
// Kernel 2: pNeRF scan; state (bc, N, sfac) with mh = sfac*(N x bc)
// folded in algebraically (stable Newton-corrected normalization).
//   G = N x bc;  Y = c1*G + c2*N;  d = sfac*Y + rc*bc
//   bc' = d/r (analytic);  N' = bc x d;  sfac' = nA - nB*|N'|^2
// =====================================================================
__global__ __launch_bounds__(64) void k_scan(const float* __restrict__ bl,
                                             const float* __restrict__ ba)
{
    __shared__ float2 sc[(FLEN + 2) * SCAN_CHB];         // 28.2 KB static
    int tid = threadIdx.x;
    int chain0 = blockIdx.x * SCAN_CHB;
    for (int idx = tid; idx < (FLEN + 2) * SCAN_CHB; idx += 64) {
        int lsr = idx >> 3;
        int lane = idx & 7;
        sc[idx] = (lsr < FLEN) ? g_c2[lsr * NCH + chain0 + lane]
                               : make_float2(0.f, 0.f);
    }
    __syncthreads();
    if (tid >= SCAN_CHB) return;
    int chain = chain0 + tid;
    int f = chain >> 6, b = chain & 63;
    int ph = f % 3;

    float rcA[3], irA[3], nA[3], nB[3];
#pragma unroll
    for (int k = 0; k < 3; k++) {
        int j = ph + k; if (j >= 3) j -= 3;
        float r = bl[j], t = ba[j];
        rcA[k] = r * cosf(t);
        irA[k] = 1.f / r;
        float x0 = 1.f / (r * sinf(t));
        nA[k] = 1.5f * x0;
        nB[k] = 0.5f * x0 * x0 * x0;
    }

    // init: bc=(1,0,0), n=(0,0,1) -> N=(0,0,1), sfac=1 (mh=(0,1,0) implied)
    float bcx = 1.f, bcy = 0.f, bcz = 0.f;
    float Nx  = 0.f, Ny  = 0.f, Nz  = 1.f;
    float sfac = 1.f;
    float Cx = 0.f, Cy = 0.f, Cz = 0.f;

    float* outp = &g_coords[(((size_t)f * FLEN) * B_Q + b) * 3];
    const float2* pp = sc + tid;
    float2 pa = pp[0];
    float2 pb = pp[SCAN_CHB];
    int l = 0;

#define SCAN_STEP(k)                                                         \
    {                                                                        \
        float2 cc = pa; pa = pb; pb = pp[(l + 2) * SCAN_CHB];                \
        float Gx = fmaf(Ny, bcz, -(Nz * bcy));                               \
        float Gy = fmaf(Nz, bcx, -(Nx * bcz));                               \
        float Gz = fmaf(Nx, bcy, -(Ny * bcx));                               \
        float Yx = fmaf(cc.x, Gx, cc.y * Nx);                                \
        float Yy = fmaf(cc.x, Gy, cc.y * Ny);                                \
        float Yz = fmaf(cc.x, Gz, cc.y * Nz);                                \
        float dx = fmaf(sfac, Yx, rcA[k] * bcx);                             \
        float dy = fmaf(sfac, Yy, rcA[k] * bcy);                             \
        float dz = fmaf(sfac, Yz, rcA[k] * bcz);                             \
        float N2x = fmaf(bcy, dz, -(bcz * dy));                              \
        float N2y = fmaf(bcz, dx, -(bcx * dz));                              \
        float N2z = fmaf(bcx, dy, -(bcy * dx));                              \
        bcx = dx * irA[k]; bcy = dy * irA[k]; bcz = dz * irA[k];             \
        float d2 = fmaf(N2x, N2x, fmaf(N2y, N2y, N2z * N2z));                \
        sfac = fmaf(d2, -nB[k], nA[k]);                                      \
        Nx = N2x; Ny = N2y; Nz = N2z;                                        \
        Cx += dx; Cy += dy; Cz += dz;                                        \
        float* o = outp + (size_t)l * (B_Q * 3);                             \
        o[0] = Cx; o[1] = Cy; o[2] = Cz;                                     \
        ++l;                                                                 \
    }

    for (int it = 0; it < 146; ++it) { SCAN_STEP(0) SCAN_STEP(1) SCAN_STEP(2) }
    SCAN_STEP(0)                                         // 439 = 3*146 + 1
#undef SCAN_STEP
}

// =====================================================================
// Kernel 3a: per-batch cumulative fragment transforms (composed affine).
// =====================================================================
__global__ void k_align()
{
    int b = threadIdx.x;
    if (b >= B_Q) return;
    float M00=1.f,M01=0.f,M02=0.f,M10=0.f,M11=1.f,M12=0.f,M20=0.f,M21=0.f,M22=1.f;
    float tx=0.f,ty=0.f,tz=0.f;
    {
        float4* mt = &g_Mt4[(size_t)b * 3];
        mt[0] = make_float4(1.f,0.f,0.f,0.f);
        mt[1] = make_float4(1.f,0.f,0.f,0.f);
        mt[2] = make_float4(1.f,0.f,0.f,0.f);
    }
    for (int j = 0; j < NFRAG - 1; ++j) {
        const float* A = &g_coords[(((size_t)j * FLEN + (FLEN - 3)) * B_Q + b) * 3];
        const float* Bv = A + B_Q * 3;
        const float* Cv = Bv + B_Q * 3;
        float bx=Cv[0]-Bv[0], by=Cv[1]-Bv[1], bz=Cv[2]-Bv[2];
        float ax=Bv[0]-A[0],  ay=Bv[1]-A[1],  az=Bv[2]-A[2];
        float Nx=fmaf(ay,bz,-az*by), Ny=fmaf(az,bx,-ax*bz), Nz=fmaf(ax,by,-ay*bx);
        float s1=rsqrtf(fmaf(bx,bx,fmaf(by,by,bz*bz)));
        float s2=rsqrtf(fmaf(Nx,Nx,fmaf(Ny,Ny,Nz*Nz)));
        float s12=s1*s2;
        float mxv=fmaf(Ny,bz,-Nz*by)*s12;
        float myv=fmaf(Nz,bx,-Nx*bz)*s12;
        float mzv=fmaf(Nx,by,-Ny*bx)*s12;
        float bcx=bx*s1, bcy=by*s1, bcz=bz*s1;
        float nx=Nx*s2,  ny=Ny*s2,  nz=Nz*s2;
        float N00 = M00*bcx + M01*bcy + M02*bcz;
        float N10 = M10*bcx + M11*bcy + M12*bcz;
        float N20 = M20*bcx + M21*bcy + M22*bcz;
        float N01 = M00*mxv + M01*myv + M02*mzv;
        float N11 = M10*mxv + M11*myv + M12*mzv;
        float N21 = M20*mxv + M21*myv + M22*mzv;
        float N02 = M00*nx + M01*ny + M02*nz;
        float N12 = M10*nx + M11*ny + M12*nz;
        float N22 = M20*nx + M21*ny + M22*nz;
        float ntx = tx + M00*Cv[0] + M01*Cv[1] + M02*Cv[2];
        float nty = ty + M10*Cv[0] + M11*Cv[1] + M12*Cv[2];
        float ntz = tz + M20*Cv[0] + M21*Cv[1] + M22*Cv[2];
        M00=N00;M01=N01;M02=N02;M10=N10;M11=N11;M12=N12;M20=N20;M21=N21;M22=N22;
        tx=ntx;ty=nty;tz=ntz;
        float4* mt = &g_Mt4[((size_t)(j + 1) * B_Q + b) * 3];
        mt[0] = make_float4(M00,M01,M02,M10);
        mt[1] = make_float4(M11,M12,M20,M21);
        mt[2] = make_float4(M22,tx,ty,tz);
    }
}

// =====================================================================
// Kernel 3b: apply per-fragment affine; b-pair per thread (float2 IO).
// =====================================================================
__global__ __launch_bounds__(256) void k_out(float* __restrict__ out)
{
    int t = blockIdx.x * 256 + threadIdx.x;              // t < 98304
    int m = t >> 5;
    int b0 = (t & 31) * 2;
    int f = m / FLEN;
    const float2* X = (const float2*)&g_coords[((size_t)m * B_Q + b0) * 3];
    float2 x0 = X[0], x1 = X[1], x2 = X[2];
    const float4* Ma = &g_Mt4[((size_t)f * B_Q + b0) * 3];
    float4 a0 = Ma[0], a1 = Ma[1], a2 = Ma[2];
    float4 b0v = Ma[3], b1v = Ma[4], b2v = Ma[5];
    float r0x = fmaf(a0.x, x0.x, fmaf(a0.y, x0.y, fmaf(a0.z, x1.x, a2.y)));
    float r0y = fmaf(a0.w, x0.x, fmaf(a1.x, x0.y, fmaf(a1.y, x1.x, a2.z)));
    float r0z = fmaf(a1.z, x0.x, fmaf(a1.w, x0.y, fmaf(a2.x, x1.x, a2.w)));
    float r1x = fmaf(b0v.x, x1.y, fmaf(b0v.y, x2.x, fmaf(b0v.z, x2.y, b2v.y)));
    float r1y = fmaf(b0v.w, x1.y, fmaf(b1v.x, x2.x, fmaf(b1v.y, x2.y, b2v.z)));
    float r1z = fmaf(b1v.z, x1.y, fmaf(b1v.w, x2.x, fmaf(b2v.x, x2.y, b2v.w)));
    float2* O = (float2*)(out + ((size_t)m * B_Q + b0) * 3);
    O[0] = make_float2(r0x, r0y);
    O[1] = make_float2(r0z, r1x);
    O[2] = make_float2(r1y, r1z);
}

extern "C" void kernel_launch(void* const* d_in, const int* in_sizes, int n_in,
                              void* d_out, int out_size)
{
    (void)in_sizes; (void)n_in; (void)out_size;
    const float* inp   = (const float*)d_in[0];
    const float* W     = (const float*)d_in[1];
    const float* bias  = (const float*)d_in[2];
    const float* alpha = (const float*)d_in[3];
    const float* bl    = (const float*)d_in[4];
    const float* ba    = (const float*)d_in[5];
    // d_in[6] = nfrag (== 7 by construction; compile-time constant here)

    static int attr_done = 0;
    if (!attr_done) {
        cudaFuncSetAttribute(k_gemm, cudaFuncAttributeMaxDynamicSharedMemorySize, GEMM_SMEM);
        attr_done = 1;
    }

    k_gemm <<<256, 256, GEMM_SMEM>>>(inp, W, bias, alpha, bl, ba);
    k_scan <<<NCH / SCAN_CHB, 64>>>(bl, ba);              // 56 blocks * 8 chains
    k_align<<<1, 64>>>();
    k_out  <<<384, 256>>>((float*)d_out);                 // b-pair float2 IO
}

// round 13
// speedup vs baseline: 1.2095x; 1.0509x over previous
#include <cuda_runtime.h>

#define L_Q   1024
#define B_Q   64
#define D_Q   512
#define U_Q   20
#define LTOT  3072                 // 3*L
#define NFRAG 7
#define FLEN  439                  // ceil(3072/7); 7*439 = 3073, pad = 1
#define NCH   (NFRAG * B_Q)        // 448 independent scan chains
#define SCAN_CHB 8                 // chains per scan block

// GEMM (tensor): warp = 32 rows x 24 u x K=512, mma.m16n8k8 tf32 split.
#define RPW   32                   // rows per warp
#define KC    16                   // k per staged chunk (64B per row)
#define NCHK  (D_Q / KC)           // 32 chunks
#define ROWW  20                   // words per staged row (16 data + 4 pad = 80B, odd-16B)
#define ABUF  (2 * RPW * ROWW)     // per-warp double buffer words = 1280
#define WPAD  24                   // u padded to 24 (3 n-tiles of 8)
#define WS_FL (D_Q * WPAD)         // 12288 words
#define GEMM_SMEM ((WS_FL + 8 * ABUF) * 4)   // 90112 B -> 2 blocks/SM

// scan dynamic smem: staged (c1,c2) + coords accumulation buffer
#define SCAN_SC_FL  ((FLEN + 2) * SCAN_CHB * 2)          // float2 region, floats
#define SCAN_SMEM   (SCAN_SC_FL * 4 + FLEN * SCAN_CHB * 16)  // 28224 + 56192 B

// Scratch (no allocations allowed -> __device__ globals)
__device__ float2 g_c2[FLEN * NCH];                      // (c1, c2) per step, [ls][chain]
__device__ float  g_coords[(NFRAG * FLEN) * B_Q * 3];    // raw fragment coords [(f*FLEN+l)][b][3]
__device__ float4 g_Mt4[NFRAG * B_Q * 3];                // per (frag,b): [M00 M01 M02 M10][M11 M12 M20 M21][M22 tx ty tz]

static __device__ __forceinline__ unsigned smem_u32(const void* p) {
    return (unsigned)__cvta_generic_to_shared(p);
}
static __device__ __forceinline__ void cp16(unsigned dst, const void* src) {
    asm volatile("cp.async.cg.shared.global [%0], [%1], 16;"
                 :: "r"(dst), "l"(src) : "memory");
}
// tf32 "hi" via mantissa truncation (LOP3 on alu pipe; no cvt instruction).
// HMMA reads only the top 19 bits of a b32 tf32 operand, so the residual
// lo can be passed as a raw fp32 register (HW truncates it internally).
static __device__ __forceinline__ unsigned tf32_hi(float x) {
    return __float_as_uint(x) & 0xFFFFE000u;
}
static __device__ __forceinline__ void mma_tf32(float* c, const unsigned* a,
                                                unsigned b0, unsigned b1) {
    asm volatile(
        "mma.sync.aligned.m16n8k8.row.col.f32.tf32.tf32.f32 "
        "{%0,%1,%2,%3}, {%4,%5,%6,%7}, {%8,%9}, {%0,%1,%2,%3};"
        : "+f"(c[0]), "+f"(c[1]), "+f"(c[2]), "+f"(c[3])
        : "r"(a[0]), "r"(a[1]), "r"(a[2]), "r"(a[3]), "r"(b0), "r"(b1));
}

// =====================================================================
// Kernel 1: logits GEMM (65536 x 512 x 20) via tf32-split tensor mma.
// R13 change: NO cvt instructions in the mainloop. hi = bits&0xFFFFE000
// (alu), lo = x - hi (fma pipe), lo passed raw (HMMA truncates). The 28
// cvt/lane/k8 of R12 (suspected dominant cost on the slow cast pipe) are
// gone. Tiling unchanged: warp = 32 rows x 24 u x K=512, 2 m-tiles x
// 3 n-tiles x 3 split terms; warp-private cp.async double buffering.
// =====================================================================
__global__ __launch_bounds__(256, 2) void k_gemm(
    const float* __restrict__ inp, const float* __restrict__ W,
    const float* __restrict__ bias, const float* __restrict__ alpha,
    const float* __restrict__ bl, const float* __restrict__ ba)
{
    extern __shared__ float sm[];                        // [WS_FL | 8 x ABUF]
    __shared__ float sSin[U_Q * 3], sCos[U_Q * 3], sB[U_Q];
    int tid = threadIdx.x;
    int w = tid >> 5, lane = tid & 31;
    int g = lane >> 2, tg = lane & 3;

    // W into smem as sW[k][u'] (u' padded to 24 with zeros)
    for (int idx = tid; idx < WS_FL; idx += 256) {
        int k = idx / WPAD, u = idx - k * WPAD;
        sm[idx] = (u < U_Q) ? W[u * D_Q + k] : 0.f;
    }
    if (tid < U_Q * 3) { float a = alpha[tid]; sSin[tid] = sinf(a); sCos[tid] = cosf(a); }
    if (tid < U_Q) sB[tid] = bias[tid];

    // pNeRF pad element (global position 3072 -> frag 6, step ls=438):
    // its coordinate is dropped and its frame never consumed.
    if (blockIdx.x == 0 && tid < B_Q) {
        g_c2[(FLEN - 1) * NCH + 6 * B_Q + tid] = make_float2(0.1f, 0.1f);
    }

    float rs[3];
#pragma unroll
    for (int j = 0; j < 3; j++) rs[j] = bl[j] * sinf(ba[j]);

    int warpRow = blockIdx.x * 256 + w * RPW;
    const float* gsrc = inp + (size_t)warpRow * D_Q;
    float* mybuf = sm + WS_FL + w * ABUF;
    unsigned myb0 = smem_u32(mybuf);

    // stage chunk c (32 rows x 64B) into half-buffer c&1: 4 cp16/lane.
#define ISSUE(c)                                                              \
    {                                                                         \
        unsigned _b = myb0 + (unsigned)(((c) & 1) * (RPW * ROWW)) * 4u;       \
        const float* _g = gsrc + (c) * KC;                                    \
        _Pragma("unroll")                                                     \
        for (int i = 0; i < 4; i++) {                                         \
            int _idx = i * 32 + lane;                                         \
            int _r = _idx >> 2, _q = _idx & 3;                                \
            cp16(_b + (unsigned)(_r * ROWW + _q * 4) * 4u,                    \
                 _g + (size_t)_r * D_Q + _q * 4);                             \
        }                                                                     \
        asm volatile("cp.async.commit_group;" ::: "memory");                  \
    }

    ISSUE(0)
    ISSUE(1)
    __syncthreads();                                     // W / sSin ready
    asm volatile("cp.async.wait_group 1;" ::: "memory"); // chunk 0 done
    __syncwarp();

    float acc[2][3][4];
#pragma unroll
    for (int mt = 0; mt < 2; mt++)
#pragma unroll
        for (int nt = 0; nt < 3; nt++)
#pragma unroll
            for (int i = 0; i < 4; i++) acc[mt][nt][i] = 0.f;

#pragma unroll 1
    for (int c = 0; c < NCHK; ++c) {
        const float* bufw = mybuf + (c & 1) * (RPW * ROWW);
#pragma unroll
        for (int kw = 0; kw < 2; ++kw) {                 // two k8 windows per chunk
            int kb = kw * 8;
            unsigned ah[2][4], al[2][4];
#pragma unroll
            for (int mt = 0; mt < 2; mt++) {
                int r0 = mt * 16 + g, r1 = mt * 16 + 8 + g;
                float x0 = bufw[r0 * ROWW + kb + tg];
                float x1 = bufw[r1 * ROWW + kb + tg];
                float x2 = bufw[r0 * ROWW + kb + tg + 4];
                float x3 = bufw[r1 * ROWW + kb + tg + 4];
                ah[mt][0] = tf32_hi(x0); al[mt][0] = __float_as_uint(x0 - __uint_as_float(ah[mt][0]));
                ah[mt][1] = tf32_hi(x1); al[mt][1] = __float_as_uint(x1 - __uint_as_float(ah[mt][1]));
                ah[mt][2] = tf32_hi(x2); al[mt][2] = __float_as_uint(x2 - __uint_as_float(ah[mt][2]));
                ah[mt][3] = tf32_hi(x3); al[mt][3] = __float_as_uint(x3 - __uint_as_float(ah[mt][3]));
            }
            int k0 = c * KC + kb;
#pragma unroll
            for (int nt = 0; nt < 3; nt++) {
                float w0 = sm[(k0 + tg) * WPAD + nt * 8 + g];
                float w1 = sm[(k0 + tg + 4) * WPAD + nt * 8 + g];
                unsigned bh0 = tf32_hi(w0), bl0 = __float_as_uint(w0 - __uint_as_float(bh0));
                unsigned bh1 = tf32_hi(w1), bl1 = __float_as_uint(w1 - __uint_as_float(bh1));
#pragma unroll
                for (int mt = 0; mt < 2; mt++) {
                    mma_tf32(acc[mt][nt], ah[mt], bh0, bh1);   // Ah*Wh
                    mma_tf32(acc[mt][nt], al[mt], bh0, bh1);   // Al*Wh
                    mma_tf32(acc[mt][nt], ah[mt], bl0, bl1);   // Ah*Wl
                }
            }
        }
        __syncwarp();
        if (c + 2 < NCHK) {
            ISSUE(c + 2)
            asm volatile("cp.async.wait_group 1;" ::: "memory");
        } else {
            asm volatile("cp.async.wait_group 0;" ::: "memory");
        }
        __syncwarp();
    }
#undef ISSUE

    // ---- epilogue: fragments -> warp-private smem logits (stride 25) ----
    float* sL = mybuf;                                   // 1280 words >= 32*25
    __syncwarp();
#pragma unroll
    for (int mt = 0; mt < 2; mt++)
#pragma unroll
        for (int nt = 0; nt < 3; nt++) {
            int cbase = nt * 8 + tg * 2;
            sL[(mt * 16 + g) * 25 + cbase]         = acc[mt][nt][0];
            sL[(mt * 16 + g) * 25 + cbase + 1]     = acc[mt][nt][1];
            sL[(mt * 16 + g + 8) * 25 + cbase]     = acc[mt][nt][2];
            sL[(mt * 16 + g + 8) * 25 + cbase + 1] = acc[mt][nt][3];
        }
    __syncwarp();

    {
        float lg[U_Q];
        float mx = -1e30f;
#pragma unroll
        for (int u = 0; u < U_Q; u++) {
            lg[u] = sL[lane * 25 + u] + sB[u];
            mx = fmaxf(mx, lg[u]);
        }
        // softmax numerator only: cos/sin(phi) from (s,c) ratio; softmax
        // normalization cancels.
        float sj[3] = {0.f,0.f,0.f}, cj[3] = {0.f,0.f,0.f};
#pragma unroll
        for (int u = 0; u < U_Q; u++) {
            float e = __expf(lg[u] - mx);
#pragma unroll
            for (int j = 0; j < 3; j++) {
                sj[j] = fmaf(e, sSin[u*3+j], sj[j]);
                cj[j] = fmaf(e, sCos[u*3+j], cj[j]);
            }
        }
        int row = warpRow + lane;
        int l = row >> 6, b = row & 63;
#pragma unroll
        for (int j = 0; j < 3; j++) {
            float sv = sj[j], c2v = cj[j];
            float rn = rsqrtf(fmaf(sv, sv, c2v * c2v));
            int m  = 3 * l + j;
            int f  = m / FLEN;
            int ls = m - f * FLEN;
            g_c2[ls * NCH + f * B_Q + b] =
                make_float2(rs[j] * (c2v * rn), rs[j] * (sv * rn));
        }
    }
}

// =====================================================================
// Kernel 2: pNeRF scan (stable Newton-corrected frame recurrence).
// R13 change: per-step output goes to smem via ONE STS.128 (issue ~4cyc)
// instead of 3 STG.32 (15cyc) -- the lone active warp is issue-bound, so
// this cuts ~10 cyc/step. Coords flushed to global cooperatively at end.
// =====================================================================
__global__ __launch_bounds__(64) void k_scan(const float* __restrict__ bl,
                                             const float* __restrict__ ba)
{
    extern __shared__ float sdyn[];
    float2* sc = (float2*)sdyn;                          // [(FLEN+2)][8]
    float4* scoords = (float4*)(sdyn + SCAN_SC_FL);      // [FLEN][8]
    int tid = threadIdx.x;
    int chain0 = blockIdx.x * SCAN_CHB;
    for (int idx = tid; idx < (FLEN + 2) * SCAN_CHB; idx += 64) {
        int lsr = idx >> 3;
        int lane = idx & 7;
        sc[idx] = (lsr < FLEN) ? g_c2[lsr * NCH + chain0 + lane]
                               : make_float2(0.f, 0.f);
    }
    __syncthreads();
    int f = chain0 >> 6, b0 = chain0 & 63;               // all 8 chains share f

    if (tid < SCAN_CHB) {
        int ph = f % 3;
        float rcA[3], irA[3], nA[3], nB[3];
#pragma unroll
        for (int k = 0; k < 3; k++) {
            int j = ph + k; if (j >= 3) j -= 3;
            float r = bl[j], t = ba[j];
            rcA[k] = r * cosf(t);
            irA[k] = 1.f / r;
            float x0 = 1.f / (r * sinf(t));
            nA[k] = 1.5f * x0;
            nB[k] = 0.5f * x0 * x0 * x0;
        }

        // init: bc=(1,0,0), n=(0,0,1) -> N=(0,0,1), sfac=1
        float bcx = 1.f, bcy = 0.f, bcz = 0.f;
        float Nx  = 0.f, Ny  = 0.f, Nz  = 1.f;
        float sfac = 1.f;
        float Cx = 0.f, Cy = 0.f, Cz = 0.f;

        const float2* pp = sc + tid;
        float2 pa = pp[0];
        float2 pb = pp[SCAN_CHB];
        int l = 0;

#define SCAN_STEP(k)                                                         \
        {                                                                    \
            float2 cc = pa; pa = pb; pb = pp[(l + 2) * SCAN_CHB];            \
            float Gx = fmaf(Ny, bcz, -(Nz * bcy));                           \
            float Gy = fmaf(Nz, bcx, -(Nx * bcz));                           \
            float Gz = fmaf(Nx, bcy, -(Ny * bcx));                           \
            float Yx = fmaf(cc.x, Gx, cc.y * Nx);                            \
            float Yy = fmaf(cc.x, Gy, cc.y * Ny);                            \
            float Yz = fmaf(cc.x, Gz, cc.y * Nz);                            \
            float dx = fmaf(sfac, Yx, rcA[k] * bcx);                         \
            float dy = fmaf(sfac, Yy, rcA[k] * bcy);                         \
            float dz = fmaf(sfac, Yz, rcA[k] * bcz);                         \
            float N2x = fmaf(bcy, dz, -(bcz * dy));                          \
            float N2y = fmaf(bcz, dx, -(bcx * dz));                          \
            float N2z = fmaf(bcx, dy, -(bcy * dx));                          \
            bcx = dx * irA[k]; bcy = dy * irA[k]; bcz = dz * irA[k];         \
            float d2 = fmaf(N2x, N2x, fmaf(N2y, N2y, N2z * N2z));            \
            sfac = fmaf(d2, -nB[k], nA[k]);                                  \
            Nx = N2x; Ny = N2y; Nz = N2z;                                    \
            Cx += dx; Cy += dy; Cz += dz;                                    \
            scoords[l * SCAN_CHB + tid] = make_float4(Cx, Cy, Cz, 0.f);      \
            ++l;                                                             \
        }

        for (int it = 0; it < 146; ++it) { SCAN_STEP(0) SCAN_STEP(1) SCAN_STEP(2) }
        SCAN_STEP(0)                                     // 439 = 3*146 + 1
#undef SCAN_STEP
    }
    __syncthreads();

    // flush coords: smem float4[l][8] -> global packed [l][8 chains][3]
    float* gdst = &g_coords[(((size_t)f * FLEN) * B_Q + b0) * 3];
    for (int idx = tid; idx < FLEN * 24; idx += 64) {
        int l = idx / 24, wd = idx - l * 24;
        int ch = wd / 3, comp = wd - ch * 3;
        gdst[(size_t)l * (B_Q * 3) + wd] =
            ((const float*)&scoords[l * SCAN_CHB + ch])[comp];
    }
}

// =====================================================================
// Kernel 3a: per-batch cumulative fragment transforms (composed affine).
// =====================================================================
__global__ void k_align()
{
    int b = threadIdx.x;
    if (b >= B_Q) return;
    float M00=1.f,M01=0.f,M02=0.f,M10=0.f,M11=1.f,M12=0.f,M20=0.f,M21=0.f,M22=1.f;
    float tx=0.f,ty=0.f,tz=0.f;
    {
        float4* mt = &g_Mt4[(size_t)b * 3];
        mt[0] = make_float4(1.f,0.f,0.f,0.f);
        mt[1] = make_float4(1.f,0.f,0.f,0.f);
        mt[2] = make_float4(1.f,0.f,0.f,0.f);
    }
    for (int j = 0; j < NFRAG - 1; ++j) {
        const float* A = &g_coords[(((size_t)j * FLEN + (FLEN - 3)) * B_Q + b) * 3];
        const float* Bv = A + B_Q * 3;
        const float* Cv = Bv + B_Q * 3;
        float bx=Cv[0]-Bv[0], by=Cv[1]-Bv[1], bz=Cv[2]-Bv[2];
        float ax=Bv[0]-A[0],  ay=Bv[1]-A[1],  az=Bv[2]-A[2];
        float Nx=fmaf(ay,bz,-az*by), Ny=fmaf(az,bx,-ax*bz), Nz=fmaf(ax,by,-ay*bx);
        float s1=rsqrtf(fmaf(bx,bx,fmaf(by,by,bz*bz)));
        float s2=rsqrtf(fmaf(Nx,Nx,fmaf(Ny,Ny,Nz*Nz)));
        float s12=s1*s2;
        float mxv=fmaf(Ny,bz,-Nz*by)*s12;
        float myv=fmaf(Nz,bx,-Nx*bz)*s12;
        float mzv=fmaf(Nx,by,-Ny*bx)*s12;
        float bcx=bx*s1, bcy=by*s1, bcz=bz*s1;
        float nx=Nx*s2,  ny=Ny*s2,  nz=Nz*s2;
        float N00 = M00*bcx + M01*bcy + M02*bcz;
        float N10 = M10*bcx + M11*bcy + M12*bcz;
        float N20 = M20*bcx + M21*bcy + M22*bcz;
        float N01 = M00*mxv + M01*myv + M02*mzv;
        float N11 = M10*mxv + M11*myv + M12*mzv;
        float N21 = M20*mxv + M21*myv + M22*mzv;
        float N02 = M00*nx + M01*ny + M02*nz;
        float N12 = M10*nx + M11*ny + M12*nz;
        float N22 = M20*nx + M21*ny + M22*nz;
        float ntx = tx + M00*Cv[0] + M01*Cv[1] + M02*Cv[2];
        float nty = ty + M10*Cv[0] + M11*Cv[1] + M12*Cv[2];
        float ntz = tz + M20*Cv[0] + M21*Cv[1] + M22*Cv[2];
        M00=N00;M01=N01;M02=N02;M10=N10;M11=N11;M12=N12;M20=N20;M21=N21;M22=N22;
        tx=ntx;ty=nty;tz=ntz;
        float4* mt = &g_Mt4[((size_t)(j + 1) * B_Q + b) * 3];
        mt[0] = make_float4(M00,M01,M02,M10);
        mt[1] = make_float4(M11,M12,M20,M21);
        mt[2] = make_float4(M22,tx,ty,tz);
    }
}

// =====================================================================
// Kernel 3b: apply per-fragment affine; b-pair per thread (float2 IO).
// =====================================================================
__global__ __launch_bounds__(256) void k_out(float* __restrict__ out)
{
    int t = blockIdx.x * 256 + threadIdx.x;              // t < 98304
    int m = t >> 5;
    int b0 = (t & 31) * 2;
    int f = m / FLEN;
    const float2* X = (const float2*)&g_coords[((size_t)m * B_Q + b0) * 3];
    float2 x0 = X[0], x1 = X[1], x2 = X[2];
    const float4* Ma = &g_Mt4[((size_t)f * B_Q + b0) * 3];
    float4 a0 = Ma[0], a1 = Ma[1], a2 = Ma[2];
    float4 b0v = Ma[3], b1v = Ma[4], b2v = Ma[5];
    float r0x = fmaf(a0.x, x0.x, fmaf(a0.y, x0.y, fmaf(a0.z, x1.x, a2.y)));
    float r0y = fmaf(a0.w, x0.x, fmaf(a1.x, x0.y, fmaf(a1.y, x1.x, a2.z)));
    float r0z = fmaf(a1.z, x0.x, fmaf(a1.w, x0.y, fmaf(a2.x, x1.x, a2.w)));
    float r1x = fmaf(b0v.x, x1.y, fmaf(b0v.y, x2.x, fmaf(b0v.z, x2.y, b2v.y)));
    float r1y = fmaf(b0v.w, x1.y, fmaf(b1v.x, x2.x, fmaf(b1v.y, x2.y, b2v.z)));
    float r1z = fmaf(b1v.z, x1.y, fmaf(b1v.w, x2.x, fmaf(b2v.x, x2.y, b2v.w)));
    float2* O = (float2*)(out + ((size_t)m * B_Q + b0) * 3);
    O[0] = make_float2(r0x, r0y);
    O[1] = make_float2(r0z, r1x);
    O[2] = make_float2(r1y, r1z);
}

extern "C" void kernel_launch(void* const* d_in, const int* in_sizes, int n_in,
                              void* d_out, int out_size)
{
    (void)in_sizes; (void)n_in; (void)out_size;
    const float* inp   = (const float*)d_in[0];
    const float* W     = (const float*)d_in[1];
    const float* bias  = (const float*)d_in[2];
    const float* alpha = (const float*)d_in[3];
    const float* bl    = (const float*)d_in[4];
    const float* ba    = (const float*)d_in[5];
    // d_in[6] = nfrag (== 7 by construction; compile-time constant here)

    static int attr_done = 0;
    if (!attr_done) {
        cudaFuncSetAttribute(k_gemm, cudaFuncAttributeMaxDynamicSharedMemorySize, GEMM_SMEM);
        cudaFuncSetAttribute(k_scan, cudaFuncAttributeMaxDynamicSharedMemorySize, SCAN_SMEM);
        attr_done = 1;
    }

    k_gemm <<<256, 256, GEMM_SMEM>>>(inp, W, bias, alpha, bl, ba);
    k_scan <<<NCH / SCAN_CHB, 64, SCAN_SMEM>>>(bl, ba);   // 56 blocks * 8 chains
    k_align<<<1, 64>>>();
    k_out  <<<384, 256>>>((float*)d_out);                 // b-pair float2 IO
}

// round 14
// speedup vs baseline: 1.3855x; 1.1455x over previous
#include <cuda_runtime.h>

#define L_Q   1024
#define B_Q   64
#define D_Q   512
#define U_Q   20
#define LTOT  3072                 // 3*L
#define NFRAG 7
#define FLEN  439                  // ceil(3072/7); 7*439 = 3073, pad = 1
#define NCH   (NFRAG * B_Q)        // 448 chains; split x2 -> 896 half-chains
#define SCAN_CHB 8                 // chains per scan block
#define HLEN1 220                  // half1 steps (ls 0..219)
#define HLEN2 219                  // half2 steps (ls 220..438)

// GEMM (tensor): warp = 32 rows x 24 u x K=512, mma.m16n8k8 tf32 split.
#define RPW   32
#define KC    16
#define NCHK  (D_Q / KC)           // 32 chunks
#define ROWW  20                   // 16 data + 4 pad = 80B rows (odd-16B)
#define ABUF  (2 * RPW * ROWW)     // 1280 words per warp
#define WPAD  24
#define WS_FL (D_Q * WPAD)         // 12288 words
#define GEMM_SMEM ((WS_FL + 8 * ABUF) * 4)   // 90112 B -> 2 blocks/SM

// scan dynamic smem: staged (c1,c2) + coords buffer (max half = 220)
#define SCAN_SC_FL  ((HLEN1 + 2) * SCAN_CHB * 2)
#define SCAN_SMEM   (SCAN_SC_FL * 4 + HLEN1 * SCAN_CHB * 16)   // 42368 B

// Scratch (no allocations allowed -> __device__ globals)
__device__ float2 g_c2[FLEN * NCH];                      // (c1, c2) per step
__device__ float  g_coords[(NFRAG * FLEN) * B_Q * 3];    // half2 region stores LOCAL coords
__device__ float  g_half[NFRAG * B_Q * 12];              // per chain: bc(3) mh(3) n(3) C(3)
__device__ float4 g_Mt2[NFRAG * 2 * B_Q * 3];            // per (frag,half,b) affine

static __device__ __forceinline__ unsigned smem_u32(const void* p) {
    return (unsigned)__cvta_generic_to_shared(p);
}
static __device__ __forceinline__ void cp16(unsigned dst, const void* src) {
    asm volatile("cp.async.cg.shared.global [%0], [%1], 16;"
                 :: "r"(dst), "l"(src) : "memory");
}
static __device__ __forceinline__ unsigned tf32_hi(float x) {
    return __float_as_uint(x) & 0xFFFFE000u;
}
// Non-volatile: pure register op; lets ptxas interleave independent mmas.
static __device__ __forceinline__ void mma_tf32(float* c, const unsigned* a,
                                                unsigned b0, unsigned b1) {
    asm("mma.sync.aligned.m16n8k8.row.col.f32.tf32.tf32.f32 "
        "{%0,%1,%2,%3}, {%4,%5,%6,%7}, {%8,%9}, {%0,%1,%2,%3};"
        : "+f"(c[0]), "+f"(c[1]), "+f"(c[2]), "+f"(c[3])
        : "r"(a[0]), "r"(a[1]), "r"(a[2]), "r"(a[3]), "r"(b0), "r"(b1));
}

// =====================================================================
// Kernel 1: logits GEMM via tf32-split tensor mma (as R13) with the mma
// issue order restructured: all operands prepped, then the 3 split terms
// issued TERM-MAJOR so 6 independent accumulators separate every reuse
// of the same acc (R13 had 3 back-to-back RAW-dependent mmas per group,
// pinned in order by asm volatile).
// =====================================================================
__global__ __launch_bounds__(256, 2) void k_gemm(
    const float* __restrict__ inp, const float* __restrict__ W,
    const float* __restrict__ bias, const float* __restrict__ alpha,
    const float* __restrict__ bl, const float* __restrict__ ba)
{
    extern __shared__ float sm[];                        // [WS_FL | 8 x ABUF]
    __shared__ float sSin[U_Q * 3], sCos[U_Q * 3], sB[U_Q];
    int tid = threadIdx.x;
    int w = tid >> 5, lane = tid & 31;
    int g = lane >> 2, tg = lane & 3;

    for (int idx = tid; idx < WS_FL; idx += 256) {
        int k = idx / WPAD, u = idx - k * WPAD;
        sm[idx] = (u < U_Q) ? W[u * D_Q + k] : 0.f;
    }
    if (tid < U_Q * 3) { float a = alpha[tid]; sSin[tid] = sinf(a); sCos[tid] = cosf(a); }
    if (tid < U_Q) sB[tid] = bias[tid];

    if (blockIdx.x == 0 && tid < B_Q) {                  // pad element (dropped)
        g_c2[(FLEN - 1) * NCH + 6 * B_Q + tid] = make_float2(0.1f, 0.1f);
    }

    float rs[3];
#pragma unroll
    for (int j = 0; j < 3; j++) rs[j] = bl[j] * sinf(ba[j]);

    int warpRow = blockIdx.x * 256 + w * RPW;
    const float* gsrc = inp + (size_t)warpRow * D_Q;
    float* mybuf = sm + WS_FL + w * ABUF;
    unsigned myb0 = smem_u32(mybuf);

#define ISSUE(c)                                                              \
    {                                                                         \
        unsigned _b = myb0 + (unsigned)(((c) & 1) * (RPW * ROWW)) * 4u;       \
        const float* _g = gsrc + (c) * KC;                                    \
        _Pragma("unroll")                                                     \
        for (int i = 0; i < 4; i++) {                                         \
            int _idx = i * 32 + lane;                                         \
            int _r = _idx >> 2, _q = _idx & 3;                                \
            cp16(_b + (unsigned)(_r * ROWW + _q * 4) * 4u,                    \
                 _g + (size_t)_r * D_Q + _q * 4);                             \
        }                                                                     \
        asm volatile("cp.async.commit_group;" ::: "memory");                  \
    }

    ISSUE(0)
    ISSUE(1)
    __syncthreads();
    asm volatile("cp.async.wait_group 1;" ::: "memory");
    __syncwarp();

    float acc[2][3][4];
#pragma unroll
    for (int mt = 0; mt < 2; mt++)
#pragma unroll
        for (int nt = 0; nt < 3; nt++)
#pragma unroll
            for (int i = 0; i < 4; i++) acc[mt][nt][i] = 0.f;

#pragma unroll 1
    for (int c = 0; c < NCHK; ++c) {
        const float* bufw = mybuf + (c & 1) * (RPW * ROWW);
#pragma unroll
        for (int kw = 0; kw < 2; ++kw) {
            int kb = kw * 8;
            unsigned ah[2][4], al[2][4];
#pragma unroll
            for (int mt = 0; mt < 2; mt++) {
                int r0 = mt * 16 + g, r1 = mt * 16 + 8 + g;
                float x0 = bufw[r0 * ROWW + kb + tg];
                float x1 = bufw[r1 * ROWW + kb + tg];
                float x2 = bufw[r0 * ROWW + kb + tg + 4];
                float x3 = bufw[r1 * ROWW + kb + tg + 4];
                ah[mt][0] = tf32_hi(x0); al[mt][0] = __float_as_uint(x0 - __uint_as_float(ah[mt][0]));
                ah[mt][1] = tf32_hi(x1); al[mt][1] = __float_as_uint(x1 - __uint_as_float(ah[mt][1]));
                ah[mt][2] = tf32_hi(x2); al[mt][2] = __float_as_uint(x2 - __uint_as_float(ah[mt][2]));
                ah[mt][3] = tf32_hi(x3); al[mt][3] = __float_as_uint(x3 - __uint_as_float(ah[mt][3]));
            }
            int k0 = c * KC + kb;
            unsigned bh[3][2], blo[3][2];
#pragma unroll
            for (int nt = 0; nt < 3; nt++) {
                float w0 = sm[(k0 + tg) * WPAD + nt * 8 + g];
                float w1 = sm[(k0 + tg + 4) * WPAD + nt * 8 + g];
                bh[nt][0] = tf32_hi(w0); blo[nt][0] = __float_as_uint(w0 - __uint_as_float(bh[nt][0]));
                bh[nt][1] = tf32_hi(w1); blo[nt][1] = __float_as_uint(w1 - __uint_as_float(bh[nt][1]));
            }
            // term-major issue: 6 independent accs between same-acc reuse
#pragma unroll
            for (int nt = 0; nt < 3; nt++)
#pragma unroll
                for (int mt = 0; mt < 2; mt++)
                    mma_tf32(acc[mt][nt], ah[mt], bh[nt][0], bh[nt][1]);
#pragma unroll
            for (int nt = 0; nt < 3; nt++)
#pragma unroll
                for (int mt = 0; mt < 2; mt++)
                    mma_tf32(acc[mt][nt], al[mt], bh[nt][0], bh[nt][1]);
#pragma unroll
            for (int nt = 0; nt < 3; nt++)
#pragma unroll
                for (int mt = 0; mt < 2; mt++)
                    mma_tf32(acc[mt][nt], ah[mt], blo[nt][0], blo[nt][1]);
        }
        __syncwarp();
        if (c + 2 < NCHK) {
            ISSUE(c + 2)
            asm volatile("cp.async.wait_group 1;" ::: "memory");
        } else {
            asm volatile("cp.async.wait_group 0;" ::: "memory");
        }
        __syncwarp();
    }
#undef ISSUE

    float* sL = mybuf;
    __syncwarp();
#pragma unroll
    for (int mt = 0; mt < 2; mt++)
#pragma unroll
        for (int nt = 0; nt < 3; nt++) {
            int cbase = nt * 8 + tg * 2;
            sL[(mt * 16 + g) * 25 + cbase]         = acc[mt][nt][0];
            sL[(mt * 16 + g) * 25 + cbase + 1]     = acc[mt][nt][1];
            sL[(mt * 16 + g + 8) * 25 + cbase]     = acc[mt][nt][2];
            sL[(mt * 16 + g + 8) * 25 + cbase + 1] = acc[mt][nt][3];
        }
    __syncwarp();

    {
        float lg[U_Q];
        float mx = -1e30f;
#pragma unroll
        for (int u = 0; u < U_Q; u++) {
            lg[u] = sL[lane * 25 + u] + sB[u];
            mx = fmaxf(mx, lg[u]);
        }
        float sj[3] = {0.f,0.f,0.f}, cj[3] = {0.f,0.f,0.f};
#pragma unroll
        for (int u = 0; u < U_Q; u++) {
            float e = __expf(lg[u] - mx);
#pragma unroll
            for (int j = 0; j < 3; j++) {
                sj[j] = fmaf(e, sSin[u*3+j], sj[j]);
                cj[j] = fmaf(e, sCos[u*3+j], cj[j]);
            }
        }
        int row = warpRow + lane;
        int l = row >> 6, b = row & 63;
#pragma unroll
        for (int j = 0; j < 3; j++) {
            float sv = sj[j], c2v = cj[j];
            float rn = rsqrtf(fmaf(sv, sv, c2v * c2v));
            int m  = 3 * l + j;
            int f  = m / FLEN;
            int ls = m - f * FLEN;
            g_c2[ls * NCH + f * B_Q + b] =
                make_float2(rs[j] * (c2v * rn), rs[j] * (sv * rn));
        }
    }
}

// =====================================================================
// Kernel 2: pNeRF scan, chain-split x2 (rotation-equivariant recurrence).
// Blocks 0..55: half1 (ls 0..219) from canonical init; stores end frame
// (bc, mh, n) + C to g_half. Blocks 56..111: half2 (ls 220..438) from
// canonical init with matched invariants (|N|=rs_prev, sfac=1/rs_prev);
// coords stored LOCAL, realigned later via the per-chain rigid (Q, C).
// =====================================================================
__global__ __launch_bounds__(64) void k_scan(const float* __restrict__ bl,
                                             const float* __restrict__ ba)
{
    extern __shared__ float sdyn[];
    float2* sc = (float2*)sdyn;
    float4* scoords = (float4*)(sdyn + SCAN_SC_FL);
    int tid = threadIdx.x;
    int isH2 = (blockIdx.x >= 56);
    int chain0 = (blockIdx.x - (isH2 ? 56 : 0)) * SCAN_CHB;
    int lsBase = isH2 ? HLEN1 : 0;
    int steps  = isH2 ? HLEN2 : HLEN1;
    int f = chain0 >> 6, b0 = chain0 & 63;               // all 8 chains share f

    for (int idx = tid; idx < (steps + 2) * SCAN_CHB; idx += 64) {
        int lsr = idx >> 3;
        int lane = idx & 7;
        int lsg = lsBase + lsr;
        sc[idx] = (lsg < FLEN) ? g_c2[lsg * NCH + chain0 + lane]
                               : make_float2(0.f, 0.f);
    }
    __syncthreads();

    if (tid < SCAN_CHB) {
        int ph = (f + lsBase) % 3;
        float rcA[3], irA[3], nA[3], nB[3];
#pragma unroll
        for (int k = 0; k < 3; k++) {
            int j = ph + k; if (j >= 3) j -= 3;
            float r = bl[j], t = ba[j];
            rcA[k] = r * cosf(t);
            irA[k] = 1.f / r;
            float x0 = 1.f / (r * sinf(t));
            nA[k] = 1.5f * x0;
            nB[k] = 0.5f * x0 * x0 * x0;
        }

        float bcx = 1.f, bcy = 0.f, bcz = 0.f;
        float Nx = 0.f, Ny = 0.f, Nz;
        float sfac;
        if (isH2) {
            int jp = f % 3;                              // bond of step ls=219
            float rsp = bl[jp] * sinf(ba[jp]);
            Nz = rsp; sfac = 1.f / rsp;                  // matched invariants
        } else {
            Nz = 1.f; sfac = 1.f;                        // canonical init frame
        }
        float Cx = 0.f, Cy = 0.f, Cz = 0.f;

        const float2* pp = sc + tid;
        float2 pa = pp[0];
        float2 pb = pp[SCAN_CHB];
        int l = 0;

#define SCAN_STEP(k)                                                         \
        {                                                                    \
            float2 cc = pa; pa = pb; pb = pp[(l + 2) * SCAN_CHB];            \
            float Gx = fmaf(Ny, bcz, -(Nz * bcy));                           \
            float Gy = fmaf(Nz, bcx, -(Nx * bcz));                           \
            float Gz = fmaf(Nx, bcy, -(Ny * bcx));                           \
            float Yx = fmaf(cc.x, Gx, cc.y * Nx);                            \
            float Yy = fmaf(cc.x, Gy, cc.y * Ny);                            \
            float Yz = fmaf(cc.x, Gz, cc.y * Nz);                            \
            float dx = fmaf(sfac, Yx, rcA[k] * bcx);                         \
            float dy = fmaf(sfac, Yy, rcA[k] * bcy);                         \
            float dz = fmaf(sfac, Yz, rcA[k] * bcz);                         \
            float N2x = fmaf(bcy, dz, -(bcz * dy));                          \
            float N2y = fmaf(bcz, dx, -(bcx * dz));                          \
            float N2z = fmaf(bcx, dy, -(bcy * dx));                          \
            bcx = dx * irA[k]; bcy = dy * irA[k]; bcz = dz * irA[k];         \
            float d2 = fmaf(N2x, N2x, fmaf(N2y, N2y, N2z * N2z));            \
            sfac = fmaf(d2, -nB[k], nA[k]);                                  \
            Nx = N2x; Ny = N2y; Nz = N2z;                                    \
            Cx += dx; Cy += dy; Cz += dz;                                    \
            scoords[l * SCAN_CHB + tid] = make_float4(Cx, Cy, Cz, 0.f);      \
            ++l;                                                             \
        }

        for (int it = 0; it < 73; ++it) { SCAN_STEP(0) SCAN_STEP(1) SCAN_STEP(2) }
        if (!isH2) SCAN_STEP(0)                          // 220 = 3*73 + 1
#undef SCAN_STEP

        if (!isH2) {
            // end frame: n = N*sfac (unit to ~1e-7), mh = n x bc
            float nx = Nx * sfac, ny = Ny * sfac, nz = Nz * sfac;
            float mx = fmaf(ny, bcz, -(nz * bcy));
            float my = fmaf(nz, bcx, -(nx * bcz));
            float mz = fmaf(nx, bcy, -(ny * bcx));
            float* h = &g_half[((size_t)f * B_Q + b0 + tid) * 12];
            h[0] = bcx; h[1] = bcy; h[2] = bcz;
            h[3] = mx;  h[4] = my;  h[5] = mz;
            h[6] = nx;  h[7] = ny;  h[8] = nz;
            h[9] = Cx;  h[10] = Cy; h[11] = Cz;
        }
    }
    __syncthreads();

    float* gdst = &g_coords[(((size_t)f * FLEN + lsBase) * B_Q + b0) * 3];
    for (int idx = tid; idx < steps * 24; idx += 64) {
        int l = idx / 24, wd = idx - l * 24;
        int ch = wd / 3, comp = wd - ch * 3;
        gdst[(size_t)l * (B_Q * 3) + wd] =
            ((const float*)&scoords[l * SCAN_CHB + ch])[comp];
    }
}

// =====================================================================
// Kernel 3a: per-batch cumulative transforms, now per (frag, half).
// half1 of frag f: (M_f, t_f).  half2: (M_f*Q_f, M_f*C_f + t_f) where
// (Q_f, C_f) is the chain-split rigid realign from g_half. Fragment end
// triples (ls 436..438) are half2-LOCAL -> transformed by (Q_f, C_f)
// before the standard composition.
// =====================================================================
__global__ void k_align()
{
    int b = threadIdx.x;
    if (b >= B_Q) return;
    float M00=1.f,M01=0.f,M02=0.f,M10=0.f,M11=1.f,M12=0.f,M20=0.f,M21=0.f,M22=1.f;
    float tx=0.f,ty=0.f,tz=0.f;
    for (int f = 0; f < NFRAG; ++f) {
        const float* h = &g_half[((size_t)f * B_Q + b) * 12];
        float q00=h[0],q10=h[1],q20=h[2];                // col bc
        float q01=h[3],q11=h[4],q21=h[5];                // col mh
        float q02=h[6],q12=h[7],q22=h[8];                // col n
        float cx=h[9], cy=h[10], cz=h[11];
        // half1 affine
        float4* mt = &g_Mt2[(((size_t)f * 2 + 0) * B_Q + b) * 3];
        mt[0] = make_float4(M00,M01,M02,M10);
        mt[1] = make_float4(M11,M12,M20,M21);
        mt[2] = make_float4(M22,tx,ty,tz);
        // half2 affine = (M*Q, M*C + t)
        float P00 = M00*q00 + M01*q10 + M02*q20;
        float P01 = M00*q01 + M01*q11 + M02*q21;
        float P02 = M00*q02 + M01*q12 + M02*q22;
        float P10 = M10*q00 + M11*q10 + M12*q20;
        float P11 = M10*q01 + M11*q11 + M12*q21;
        float P12 = M10*q02 + M11*q12 + M12*q22;
        float P20 = M20*q00 + M21*q10 + M22*q20;
        float P21 = M20*q01 + M21*q11 + M22*q21;
        float P22 = M20*q02 + M21*q12 + M22*q22;
        float ux = tx + M00*cx + M01*cy + M02*cz;
        float uy = ty + M10*cx + M11*cy + M12*cz;
        float uz = tz + M20*cx + M21*cy + M22*cz;
        mt = &g_Mt2[(((size_t)f * 2 + 1) * B_Q + b) * 3];
        mt[0] = make_float4(P00,P01,P02,P10);
        mt[1] = make_float4(P11,P12,P20,P21);
        mt[2] = make_float4(P22,ux,uy,uz);

        if (f == NFRAG - 1) break;
        // fragment end triple: half2-local -> frag coords via (Q, C)
        float p[3][3];
#pragma unroll
        for (int i = 0; i < 3; i++) {
            const float* pl = &g_coords[(((size_t)f * FLEN + (FLEN - 3 + i)) * B_Q + b) * 3];
            float vx = pl[0], vy = pl[1], vz = pl[2];
            p[i][0] = cx + q00*vx + q01*vy + q02*vz;
            p[i][1] = cy + q10*vx + q11*vy + q12*vz;
            p[i][2] = cz + q20*vx + q21*vy + q22*vz;
        }
        float bx=p[2][0]-p[1][0], by=p[2][1]-p[1][1], bz=p[2][2]-p[1][2];
        float ax=p[1][0]-p[0][0], ay=p[1][1]-p[0][1], az=p[1][2]-p[0][2];
        float Nx=fmaf(ay,bz,-az*by), Ny=fmaf(az,bx,-ax*bz), Nz=fmaf(ax,by,-ay*bx);
        float s1=rsqrtf(fmaf(bx,bx,fmaf(by,by,bz*bz)));
        float s2=rsqrtf(fmaf(Nx,Nx,fmaf(Ny,Ny,Nz*Nz)));
        float s12=s1*s2;
        float mxv=fmaf(Ny,bz,-Nz*by)*s12;
        float myv=fmaf(Nz,bx,-Nx*bz)*s12;
        float mzv=fmaf(Nx,by,-Ny*bx)*s12;
        float bcx=bx*s1, bcy=by*s1, bcz=bz*s1;
        float nx=Nx*s2,  ny=Ny*s2,  nz=Nz*s2;
        float N00 = M00*bcx + M01*bcy + M02*bcz;
        float N10 = M10*bcx + M11*bcy + M12*bcz;
        float N20 = M20*bcx + M21*bcy + M22*bcz;
        float N01 = M00*mxv + M01*myv + M02*mzv;
        float N11 = M10*mxv + M11*myv + M12*mzv;
        float N21 = M20*mxv + M21*myv + M22*mzv;
        float N02 = M00*nx + M01*ny + M02*nz;
        float N12 = M10*nx + M11*ny + M12*nz;
        float N22 = M20*nx + M21*ny + M22*nz;
        float ntx = tx + M00*p[2][0] + M01*p[2][1] + M02*p[2][2];
        float nty = ty + M10*p[2][0] + M11*p[2][1] + M12*p[2][2];
        float ntz = tz + M20*p[2][0] + M21*p[2][1] + M22*p[2][2];
        M00=N00;M01=N01;M02=N02;M10=N10;M11=N11;M12=N12;M20=N20;M21=N21;M22=N22;
        tx=ntx;ty=nty;tz=ntz;
    }
}

// =====================================================================
// Kernel 3b: apply per-(frag,half) affine; b-pair per thread (float2 IO).
// =====================================================================
__global__ __launch_bounds__(256) void k_out(float* __restrict__ out)
{
    int t = blockIdx.x * 256 + threadIdx.x;              // t < 98304
    int m = t >> 5;
    int b0 = (t & 31) * 2;
    int f = m / FLEN;
    int ls = m - f * FLEN;
    int fh = f * 2 + (ls >= HLEN1 ? 1 : 0);
    const float2* X = (const float2*)&g_coords[((size_t)m * B_Q + b0) * 3];
    float2 x0 = X[0], x1 = X[1], x2 = X[2];
    const float4* Ma = &g_Mt2[((size_t)fh * B_Q + b0) * 3];
    float4 a0 = Ma[0], a1 = Ma[1], a2 = Ma[2];
    float4 b0v = Ma[3], b1v = Ma[4], b2v = Ma[5];
    float r0x = fmaf(a0.x, x0.x, fmaf(a0.y, x0.y, fmaf(a0.z, x1.x, a2.y)));
    float r0y = fmaf(a0.w, x0.x, fmaf(a1.x, x0.y, fmaf(a1.y, x1.x, a2.z)));
    float r0z = fmaf(a1.z, x0.x, fmaf(a1.w, x0.y, fmaf(a2.x, x1.x, a2.w)));
    float r1x = fmaf(b0v.x, x1.y, fmaf(b0v.y, x2.x, fmaf(b0v.z, x2.y, b2v.y)));
    float r1y = fmaf(b0v.w, x1.y, fmaf(b1v.x, x2.x, fmaf(b1v.y, x2.y, b2v.z)));
    float r1z = fmaf(b1v.z, x1.y, fmaf(b1v.w, x2.x, fmaf(b2v.x, x2.y, b2v.w)));
    float2* O = (float2*)(out + ((size_t)m * B_Q + b0) * 3);
    O[0] = make_float2(r0x, r0y);
    O[1] = make_float2(r0z, r1x);
    O[2] = make_float2(r1y, r1z);
}

extern "C" void kernel_launch(void* const* d_in, const int* in_sizes, int n_in,
                              void* d_out, int out_size)
{
    (void)in_sizes; (void)n_in; (void)out_size;
    const float* inp   = (const float*)d_in[0];
    const float* W     = (const float*)d_in[1];
    const float* bias  = (const float*)d_in[2];
    const float* alpha = (const float*)d_in[3];
    const float* bl    = (const float*)d_in[4];
    const float* ba    = (const float*)d_in[5];
    // d_in[6] = nfrag (== 7 by construction; compile-time constant here)

    static int attr_done = 0;
    if (!attr_done) {
        cudaFuncSetAttribute(k_gemm, cudaFuncAttributeMaxDynamicSharedMemorySize, GEMM_SMEM);
        cudaFuncSetAttribute(k_scan, cudaFuncAttributeMaxDynamicSharedMemorySize, SCAN_SMEM);
        attr_done = 1;
    }

    k_gemm <<<256, 256, GEMM_SMEM>>>(inp, W, bias, alpha, bl, ba);
    k_scan <<<112, 64, SCAN_SMEM>>>(bl, ba);              // 2 halves x 56 blocks
    k_align<<<1, 64>>>();
    k_out  <<<384, 256>>>((float*)d_out);                 // b-pair float2 IO
}

// round 15
// speedup vs baseline: 1.3919x; 1.0046x over previous
#include <cuda_runtime.h>

#define L_Q   1024
#define B_Q   64
#define D_Q   512
#define U_Q   20
#define LTOT  3072                 // 3*L
#define NFRAG 7
#define FLEN  439                  // ceil(3072/7); 7*439 = 3073, pad = 1
#define NCH   (NFRAG * B_Q)        // 448 chains; split x4 -> 1792 quarter-units
#define QLEN  110                  // quarter length (q3 = 109)

// GEMM (tensor): warp = 32 rows x 24 u x K=512, mma.m16n8k16 bf16 split.
#define RPW   32
#define KC    16                   // k per chunk = one k16 window
#define NCHK  (D_Q / KC)           // 32 chunks
#define ROWW  20                   // 16 data + 4 pad = 80B rows
#define ABUF  (2 * RPW * ROWW)     // 1280 words per warp
#define PW_U4 (NCHK * 3 * 32)      // packed-W uint4 entries = 3072 (12288 words)
#define GEMM_SMEM ((PW_U4 * 4 + 8 * ABUF) * 4)   // 90112 B -> 2 blocks/SM

// scan dynamic smem: staged (c1,c2) + local coords for 32 units x 110 steps
#define SCAN_SMEM ((QLEN + 2) * 32 * 8 + QLEN * 32 * 16)   // 84992 B

// Scratch (no allocations allowed -> __device__ globals)
__device__ float2 g_c2[FLEN * NCH];                      // (c1,c2) per step [ls][chain]
__device__ float  g_coords[(NFRAG * FLEN) * B_Q * 3];    // quarter-LOCAL coords
__device__ float  g_q[NFRAG * 4 * B_Q * 12];             // per (f,q,b): bc mh n C
__device__ float4 g_Mt4[NFRAG * 4 * B_Q * 3];            // per (f,q,b) affine

static __device__ __forceinline__ unsigned smem_u32(const void* p) {
    return (unsigned)__cvta_generic_to_shared(p);
}
static __device__ __forceinline__ void cp16(unsigned dst, const void* src) {
    asm volatile("cp.async.cg.shared.global [%0], [%1], 16;"
                 :: "r"(dst), "l"(src) : "memory");
}
// pack (x -> low bf16, y -> high bf16), round-to-nearest
static __device__ __forceinline__ unsigned pack2(float x, float y) {
    unsigned d;
    asm("cvt.rn.bf16x2.f32 %0, %1, %2;" : "=r"(d) : "f"(y), "f"(x));
    return d;
}
// split pair into rounded-hi packed + exact-residual-rounded-lo packed
static __device__ __forceinline__ void split2(float x, float y,
                                              unsigned& h, unsigned& l) {
    h = pack2(x, y);
    float hx = __uint_as_float(h << 16);
    float hy = __uint_as_float(h & 0xFFFF0000u);
    l = pack2(x - hx, y - hy);                           // x-hx exact (Sterbenz)
}
static __device__ __forceinline__ void mma_bf16(float* c, const unsigned* a,
                                                unsigned b0, unsigned b1) {
    asm("mma.sync.aligned.m16n8k16.row.col.f32.bf16.bf16.f32 "
        "{%0,%1,%2,%3}, {%4,%5,%6,%7}, {%8,%9}, {%0,%1,%2,%3};"
        : "+f"(c[0]), "+f"(c[1]), "+f"(c[2]), "+f"(c[3])
        : "r"(a[0]), "r"(a[1]), "r"(a[2]), "r"(a[3]), "r"(b0), "r"(b1));
}

// =====================================================================
// Kernel 1: logits GEMM via bf16 m16n8k16 3-term split (halves mma count
// vs tf32 k8 -- targets the legacy-HMMA rate wall). W pre-split once per
// block into fragment-ready packed bf16x2 (uint4/lane/nt/window): mainloop
// W cost = 3 LDS.128 per k16. A split in-register via pack/LOP/FADD.
// =====================================================================
__global__ __launch_bounds__(256, 2) void k_gemm(
    const float* __restrict__ inp, const float* __restrict__ W,
    const float* __restrict__ bias, const float* __restrict__ alpha,
    const float* __restrict__ bl, const float* __restrict__ ba)
{
    extern __shared__ float sm[];                        // [PW (12288w) | 8 x ABUF]
    __shared__ float sSin[U_Q * 3], sCos[U_Q * 3], sB[U_Q];
    int tid = threadIdx.x;
    int w = tid >> 5, lane = tid & 31;
    int g = lane >> 2, tg = lane & 3;

    // build packed W fragments: entry e = (win, nt, lane_e)
    uint4* sPW = (uint4*)sm;
    for (int e = tid; e < PW_U4; e += 256) {
        int win = e / 96, rem = e - win * 96;
        int nt = rem >> 5, le = rem & 31;
        int ge = le >> 2, tge = le & 3;
        int u = nt * 8 + ge;
        float x0 = 0.f, y0 = 0.f, x8 = 0.f, y8 = 0.f;
        if (u < U_Q) {
            const float* wp = W + (size_t)u * D_Q + win * 16 + 2 * tge;
            x0 = wp[0]; y0 = wp[1]; x8 = wp[8]; y8 = wp[9];
        }
        unsigned h0, l0, h8, l8;
        split2(x0, y0, h0, l0);
        split2(x8, y8, h8, l8);
        sPW[e] = make_uint4(h0, h8, l0, l8);
    }
    if (tid < U_Q * 3) { float a = alpha[tid]; sSin[tid] = sinf(a); sCos[tid] = cosf(a); }
    if (tid < U_Q) sB[tid] = bias[tid];

    if (blockIdx.x == 0 && tid < B_Q) {                  // pad element (dropped)
        g_c2[(FLEN - 1) * NCH + 6 * B_Q + tid] = make_float2(0.1f, 0.1f);
    }

    float rs[3];
#pragma unroll
    for (int j = 0; j < 3; j++) rs[j] = bl[j] * sinf(ba[j]);

    int warpRow = blockIdx.x * 256 + w * RPW;
    const float* gsrc = inp + (size_t)warpRow * D_Q;
    float* mybuf = sm + PW_U4 * 4 + w * ABUF;
    unsigned myb0 = smem_u32(mybuf);

#define ISSUE(c)                                                              \
    {                                                                         \
        unsigned _b = myb0 + (unsigned)(((c) & 1) * (RPW * ROWW)) * 4u;       \
        const float* _g = gsrc + (c) * KC;                                    \
        _Pragma("unroll")                                                     \
        for (int i = 0; i < 4; i++) {                                         \
            int _idx = i * 32 + lane;                                         \
            int _r = _idx >> 2, _q = _idx & 3;                                \
            cp16(_b + (unsigned)(_r * ROWW + _q * 4) * 4u,                    \
                 _g + (size_t)_r * D_Q + _q * 4);                             \
        }                                                                     \
        asm volatile("cp.async.commit_group;" ::: "memory");                  \
    }

    ISSUE(0)
    ISSUE(1)
    __syncthreads();
    asm volatile("cp.async.wait_group 1;" ::: "memory");
    __syncwarp();

    float acc[2][3][4];
#pragma unroll
    for (int mt = 0; mt < 2; mt++)
#pragma unroll
        for (int nt = 0; nt < 3; nt++)
#pragma unroll
            for (int i = 0; i < 4; i++) acc[mt][nt][i] = 0.f;

#pragma unroll 1
    for (int c = 0; c < NCHK; ++c) {
        const float* bufw = mybuf + (c & 1) * (RPW * ROWW);
        unsigned ah[2][4], al[2][4];
#pragma unroll
        for (int mt = 0; mt < 2; mt++) {
            int r0 = mt * 16 + g, r1 = mt * 16 + 8 + g;
            float2 p00 = *(const float2*)(bufw + r0 * ROWW + 2 * tg);
            float2 p10 = *(const float2*)(bufw + r1 * ROWW + 2 * tg);
            float2 p01 = *(const float2*)(bufw + r0 * ROWW + 8 + 2 * tg);
            float2 p11 = *(const float2*)(bufw + r1 * ROWW + 8 + 2 * tg);
            split2(p00.x, p00.y, ah[mt][0], al[mt][0]);
            split2(p10.x, p10.y, ah[mt][1], al[mt][1]);
            split2(p01.x, p01.y, ah[mt][2], al[mt][2]);
            split2(p11.x, p11.y, ah[mt][3], al[mt][3]);
        }
        uint4 pw[3];
#pragma unroll
        for (int nt = 0; nt < 3; nt++)
            pw[nt] = sPW[(c * 3 + nt) * 32 + lane];
        // term-major issue: 6 independent accumulators between reuse
#pragma unroll
        for (int nt = 0; nt < 3; nt++)
#pragma unroll
            for (int mt = 0; mt < 2; mt++)
                mma_bf16(acc[mt][nt], ah[mt], pw[nt].x, pw[nt].y);
#pragma unroll
        for (int nt = 0; nt < 3; nt++)
#pragma unroll
            for (int mt = 0; mt < 2; mt++)
                mma_bf16(acc[mt][nt], al[mt], pw[nt].x, pw[nt].y);
#pragma unroll
        for (int nt = 0; nt < 3; nt++)
#pragma unroll
            for (int mt = 0; mt < 2; mt++)
                mma_bf16(acc[mt][nt], ah[mt], pw[nt].z, pw[nt].w);
        __syncwarp();
        if (c + 2 < NCHK) {
            ISSUE(c + 2)
            asm volatile("cp.async.wait_group 1;" ::: "memory");
        } else {
            asm volatile("cp.async.wait_group 0;" ::: "memory");
        }
        __syncwarp();
    }
#undef ISSUE

    float* sL = mybuf;
    __syncwarp();
#pragma unroll
    for (int mt = 0; mt < 2; mt++)
#pragma unroll
        for (int nt = 0; nt < 3; nt++) {
            int cbase = nt * 8 + tg * 2;
            sL[(mt * 16 + g) * 25 + cbase]         = acc[mt][nt][0];
            sL[(mt * 16 + g) * 25 + cbase + 1]     = acc[mt][nt][1];
            sL[(mt * 16 + g + 8) * 25 + cbase]     = acc[mt][nt][2];
            sL[(mt * 16 + g + 8) * 25 + cbase + 1] = acc[mt][nt][3];
        }
    __syncwarp();

    {
        float lg[U_Q];
        float mx = -1e30f;
#pragma unroll
        for (int u = 0; u < U_Q; u++) {
            lg[u] = sL[lane * 25 + u] + sB[u];
            mx = fmaxf(mx, lg[u]);
        }
        float sj[3] = {0.f,0.f,0.f}, cj[3] = {0.f,0.f,0.f};
#pragma unroll
        for (int u = 0; u < U_Q; u++) {
            float e = __expf(lg[u] - mx);
#pragma unroll
            for (int j = 0; j < 3; j++) {
                sj[j] = fmaf(e, sSin[u*3+j], sj[j]);
                cj[j] = fmaf(e, sCos[u*3+j], cj[j]);
            }
        }
        int row = warpRow + lane;
        int l = row >> 6, b = row & 63;
#pragma unroll
        for (int j = 0; j < 3; j++) {
            float sv = sj[j], c2v = cj[j];
            float rn = rsqrtf(fmaf(sv, sv, c2v * c2v));
            int m  = 3 * l + j;
            int f  = m / FLEN;
            int ls = m - f * FLEN;
            g_c2[ls * NCH + f * B_Q + b] =
                make_float2(rs[j] * (c2v * rn), rs[j] * (sv * rn));
        }
    }
}

// =====================================================================
// Kernel 2: pNeRF scan, chain-split x4. 56 blocks x 32 units (one full
// warp computes). Block = (quarter q, 32 consecutive chains of one f).
// Quarter q>0 starts from canonical frame with matched invariants
// (|N| = rs_prev, sfac = 1/rs_prev); coords LOCAL; end frame stored for
// rigid composition in k_align.
// =====================================================================
__global__ __launch_bounds__(64) void k_scan(const float* __restrict__ bl,
                                             const float* __restrict__ ba)
{
    extern __shared__ float sdyn[];
    float2* sc = (float2*)sdyn;                          // [(QLEN+2)][32]
    float4* scoords = (float4*)(sdyn + (QLEN + 2) * 32 * 2);
    int tid = threadIdx.x;
    int q = blockIdx.x / 14, sub = blockIdx.x % 14;
    int c0 = sub * 32;
    int f = c0 >> 6, bb0 = c0 & 63;
    int lsBase = q * QLEN;
    int steps = (q == 3) ? (FLEN - 3 * QLEN) : QLEN;     // 109 or 110

    for (int idx = tid; idx < (steps + 2) * 32; idx += 64) {
        int lsr = idx >> 5, lane = idx & 31;
        int lsg = lsBase + lsr;
        sc[idx] = (lsg < FLEN) ? g_c2[lsg * NCH + c0 + lane]
                               : make_float2(0.f, 0.f);
    }
    __syncthreads();

    if (tid < 32) {
        int ph = (f + lsBase) % 3;
        float rcA[3], irA[3], nA[3], nB[3];
#pragma unroll
        for (int k = 0; k < 3; k++) {
            int j = ph + k; if (j >= 3) j -= 3;
            float r = bl[j], t = ba[j];
            rcA[k] = r * cosf(t);
            irA[k] = 1.f / r;
            float x0 = 1.f / (r * sinf(t));
            nA[k] = 1.5f * x0;
            nB[k] = 0.5f * x0 * x0 * x0;
        }

        float bcx = 1.f, bcy = 0.f, bcz = 0.f;
        float Nx = 0.f, Ny = 0.f, Nz;
        float sfac;
        if (q == 0) { Nz = 1.f; sfac = 1.f; }
        else {
            int jp = (f + lsBase - 1) % 3;
            float rsp = bl[jp] * sinf(ba[jp]);
            Nz = rsp; sfac = 1.f / rsp;
        }
        float Cx = 0.f, Cy = 0.f, Cz = 0.f;

        const float2* pp = sc + tid;
        float2 pa = pp[0];
        float2 pb = pp[32];
        int l = 0;

#define SCAN_STEP(k)                                                         \
        {                                                                    \
            float2 cc = pa; pa = pb; pb = pp[(l + 2) * 32];                  \
            float Gx = fmaf(Ny, bcz, -(Nz * bcy));                           \
            float Gy = fmaf(Nz, bcx, -(Nx * bcz));                           \
            float Gz = fmaf(Nx, bcy, -(Ny * bcx));                           \
            float Yx = fmaf(cc.x, Gx, cc.y * Nx);                            \
            float Yy = fmaf(cc.x, Gy, cc.y * Ny);                            \
            float Yz = fmaf(cc.x, Gz, cc.y * Nz);                            \
            float dx = fmaf(sfac, Yx, rcA[k] * bcx);                         \
            float dy = fmaf(sfac, Yy, rcA[k] * bcy);                         \
            float dz = fmaf(sfac, Yz, rcA[k] * bcz);                         \
            float N2x = fmaf(bcy, dz, -(bcz * dy));                          \
            float N2y = fmaf(bcz, dx, -(bcx * dz));                          \
            float N2z = fmaf(bcx, dy, -(bcy * dx));                          \
            bcx = dx * irA[k]; bcy = dy * irA[k]; bcz = dz * irA[k];         \
            float d2 = fmaf(N2x, N2x, fmaf(N2y, N2y, N2z * N2z));            \
            sfac = fmaf(d2, -nB[k], nA[k]);                                  \
            Nx = N2x; Ny = N2y; Nz = N2z;                                    \
            Cx += dx; Cy += dy; Cz += dz;                                    \
            scoords[l * 32 + tid] = make_float4(Cx, Cy, Cz, 0.f);            \
            ++l;                                                             \
        }

        for (int it = 0; it < 36; ++it) { SCAN_STEP(0) SCAN_STEP(1) SCAN_STEP(2) }
        SCAN_STEP(0)                                     // 109 = 36*3+1
        if (q != 3) SCAN_STEP(1)                         // 110 = 36*3+2
#undef SCAN_STEP

        // end frame: n = N*sfac, mh = n x bc
        float nx = Nx * sfac, ny = Ny * sfac, nz = Nz * sfac;
        float mx = fmaf(ny, bcz, -(nz * bcy));
        float my = fmaf(nz, bcx, -(nx * bcz));
        float mz = fmaf(nx, bcy, -(ny * bcx));
        float* h = &g_q[(((size_t)f * 4 + q) * B_Q + bb0 + tid) * 12];
        h[0] = bcx; h[1] = bcy; h[2] = bcz;
        h[3] = mx;  h[4] = my;  h[5] = mz;
        h[6] = nx;  h[7] = ny;  h[8] = nz;
        h[9] = Cx;  h[10] = Cy; h[11] = Cz;
    }
    __syncthreads();

    float* gdst = &g_coords[(((size_t)f * FLEN + lsBase) * B_Q + bb0) * 3];
    for (int idx = tid; idx < steps * 96; idx += 64) {
        int l = idx / 96, wd = idx - l * 96;
        int ch = wd / 3, comp = wd - ch * 3;
        gdst[(size_t)l * (B_Q * 3) + wd] =
            ((const float*)&scoords[l * 32 + ch])[comp];
    }
}

// =====================================================================
// Kernel 3a: per-batch transforms per (frag, quarter).
// Rq = E0∘..∘E_{q-1} (rigid quarter handoffs); final affine = M_f ∘ Rq.
// Fragment-end triple (q3-local) mapped by R3 before chain composition.
// =====================================================================
__global__ void k_align()
{
    int b = threadIdx.x;
    if (b >= B_Q) return;
    float M00=1.f,M01=0.f,M02=0.f,M10=0.f,M11=1.f,M12=0.f,M20=0.f,M21=0.f,M22=1.f;
    float tx=0.f,ty=0.f,tz=0.f;
    for (int f = 0; f < NFRAG; ++f) {
        // T = Rq (frag-local rigid), starts identity
        float T00=1.f,T01=0.f,T02=0.f,T10=0.f,T11=1.f,T12=0.f,T20=0.f,T21=0.f,T22=1.f;
        float ux=0.f,uy=0.f,uz=0.f;
        float R3[12];
        for (int qq = 0; qq < 4; ++qq) {
            // store affine G = M ∘ T for (f,qq)
            float G00 = M00*T00 + M01*T10 + M02*T20;
            float G01 = M00*T01 + M01*T11 + M02*T21;
            float G02 = M00*T02 + M01*T12 + M02*T22;
            float G10 = M10*T00 + M11*T10 + M12*T20;
            float G11 = M10*T01 + M11*T11 + M12*T21;
            float G12 = M10*T02 + M11*T12 + M12*T22;
            float G20 = M20*T00 + M21*T10 + M22*T20;
            float G21 = M20*T01 + M21*T11 + M22*T21;
            float G22 = M20*T02 + M21*T12 + M22*T22;
            float gx = tx + M00*ux + M01*uy + M02*uz;
            float gy = ty + M10*ux + M11*uy + M12*uz;
            float gz = tz + M20*ux + M21*uy + M22*uz;
            float4* mt = &g_Mt4[(((size_t)f * 4 + qq) * B_Q + b) * 3];
            mt[0] = make_float4(G00,G01,G02,G10);
            mt[1] = make_float4(G11,G12,G20,G21);
            mt[2] = make_float4(G22,gx,gy,gz);
            if (qq == 3) {
                R3[0]=T00;R3[1]=T01;R3[2]=T02;R3[3]=T10;R3[4]=T11;R3[5]=T12;
                R3[6]=T20;R3[7]=T21;R3[8]=T22;R3[9]=ux;R3[10]=uy;R3[11]=uz;
                break;                                   // no E3 compose needed
            }
            // T = T ∘ Eq (Eq: cols bc, mh, n; trans C) of quarter qq
            const float* h = &g_q[(((size_t)f * 4 + qq) * B_Q + b) * 12];
            float q00=h[0],q10=h[1],q20=h[2];
            float q01=h[3],q11=h[4],q21=h[5];
            float q02=h[6],q12=h[7],q22=h[8];
            float cx=h[9], cy=h[10], cz=h[11];
            float P00 = T00*q00 + T01*q10 + T02*q20;
            float P01 = T00*q01 + T01*q11 + T02*q21;
            float P02 = T00*q02 + T01*q12 + T02*q22;
            float P10 = T10*q00 + T11*q10 + T12*q20;
            float P11 = T10*q01 + T11*q11 + T12*q21;
            float P12 = T10*q02 + T11*q12 + T12*q22;
            float P20 = T20*q00 + T21*q10 + T22*q20;
            float P21 = T20*q01 + T21*q11 + T22*q21;
            float P22 = T20*q02 + T21*q12 + T22*q22;
            float nux = ux + T00*cx + T01*cy + T02*cz;
            float nuy = uy + T10*cx + T11*cy + T12*cz;
            float nuz = uz + T20*cx + T21*cy + T22*cz;
            T00=P00;T01=P01;T02=P02;T10=P10;T11=P11;T12=P12;T20=P20;T21=P21;T22=P22;
            ux=nux;uy=nuy;uz=nuz;
        }
        if (f == NFRAG - 1) break;
        // fragment-end triple: q3-local -> fragment coords via R3
        float p[3][3];
#pragma unroll
        for (int i = 0; i < 3; i++) {
            const float* pl = &g_coords[(((size_t)f * FLEN + (FLEN - 3 + i)) * B_Q + b) * 3];
            float vx = pl[0], vy = pl[1], vz = pl[2];
            p[i][0] = R3[9]  + R3[0]*vx + R3[1]*vy + R3[2]*vz;
            p[i][1] = R3[10] + R3[3]*vx + R3[4]*vy + R3[5]*vz;
            p[i][2] = R3[11] + R3[6]*vx + R3[7]*vy + R3[8]*vz;
        }
        float bx=p[2][0]-p[1][0], by=p[2][1]-p[1][1], bz=p[2][2]-p[1][2];
        float ax=p[1][0]-p[0][0], ay=p[1][1]-p[0][1], az=p[1][2]-p[0][2];
        float Nx=fmaf(ay,bz,-az*by), Ny=fmaf(az,bx,-ax*bz), Nz=fmaf(ax,by,-ay*bx);
        float s1=rsqrtf(fmaf(bx,bx,fmaf(by,by,bz*bz)));
        float s2=rsqrtf(fmaf(Nx,Nx,fmaf(Ny,Ny,Nz*Nz)));
        float s12=s1*s2;
        float mxv=fmaf(Ny,bz,-Nz*by)*s12;
        float myv=fmaf(Nz,bx,-Nx*bz)*s12;
        float mzv=fmaf(Nx,by,-Ny*bx)*s12;
        float bcx=bx*s1, bcy=by*s1, bcz=bz*s1;
        float nx=Nx*s2,  ny=Ny*s2,  nz=Nz*s2;
        float N00 = M00*bcx + M01*bcy + M02*bcz;
        float N10 = M10*bcx + M11*bcy + M12*bcz;
        float N20 = M20*bcx + M21*bcy + M22*bcz;
        float N01 = M00*mxv + M01*myv + M02*mzv;
        float N11 = M10*mxv + M11*myv + M12*mzv;
        float N21 = M20*mxv + M21*myv + M22*mzv;
        float N02 = M00*nx + M01*ny + M02*nz;
        float N12 = M10*nx + M11*ny + M12*nz;
        float N22 = M20*nx + M21*ny + M22*nz;
        float ntx = tx + M00*p[2][0] + M01*p[2][1] + M02*p[2][2];
        float nty = ty + M10*p[2][0] + M11*p[2][1] + M12*p[2][2];
        float ntz = tz + M20*p[2][0] + M21*p[2][1] + M22*p[2][2];
        M00=N00;M01=N01;M02=N02;M10=N10;M11=N11;M12=N12;M20=N20;M21=N21;M22=N22;
        tx=ntx;ty=nty;tz=ntz;
    }
}

// =====================================================================
// Kernel 3b: apply per-(frag,quarter) affine; b-pair per thread.
// =====================================================================
__global__ __launch_bounds__(256) void k_out(float* __restrict__ out)
{
    int t = blockIdx.x * 256 + threadIdx.x;              // t < 98304
    int m = t >> 5;
    int b0 = (t & 31) * 2;
    int f = m / FLEN;
    int ls = m - f * FLEN;
    int fh = f * 4 + ls / QLEN;                          // 438/110 = 3 max
    const float2* X = (const float2*)&g_coords[((size_t)m * B_Q + b0) * 3];
    float2 x0 = X[0], x1 = X[1], x2 = X[2];
    const float4* Ma = &g_Mt4[((size_t)fh * B_Q + b0) * 3];
    float4 a0 = Ma[0], a1 = Ma[1], a2 = Ma[2];
    float4 b0v = Ma[3], b1v = Ma[4], b2v = Ma[5];
    float r0x = fmaf(a0.x, x0.x, fmaf(a0.y, x0.y, fmaf(a0.z, x1.x, a2.y)));
    float r0y = fmaf(a0.w, x0.x, fmaf(a1.x, x0.y, fmaf(a1.y, x1.x, a2.z)));
    float r0z = fmaf(a1.z, x0.x, fmaf(a1.w, x0.y, fmaf(a2.x, x1.x, a2.w)));
    float r1x = fmaf(b0v.x, x1.y, fmaf(b0v.y, x2.x, fmaf(b0v.z, x2.y, b2v.y)));
    float r1y = fmaf(b0v.w, x1.y, fmaf(b1v.x, x2.x, fmaf(b1v.y, x2.y, b2v.z)));
    float r1z = fmaf(b1v.z, x1.y, fmaf(b1v.w, x2.x, fmaf(b2v.x, x2.y, b2v.w)));
    float2* O = (float2*)(out + ((size_t)m * B_Q + b0) * 3);
    O[0] = make_float2(r0x, r0y);
    O[1] = make_float2(r0z, r1x);
    O[2] = make_float2(r1y, r1z);
}

extern "C" void kernel_launch(void* const* d_in, const int* in_sizes, int n_in,
                              void* d_out, int out_size)
{
    (void)in_sizes; (void)n_in; (void)out_size;
    const float* inp   = (const float*)d_in[0];
    const float* W     = (const float*)d_in[1];
    const float* bias  = (const float*)d_in[2];
    const float* alpha = (const float*)d_in[3];
    const float* bl    = (const float*)d_in[4];
    const float* ba    = (const float*)d_in[5];
    // d_in[6] = nfrag (== 7 by construction; compile-time constant here)

    static int attr_done = 0;
    if (!attr_done) {
        cudaFuncSetAttribute(k_gemm, cudaFuncAttributeMaxDynamicSharedMemorySize, GEMM_SMEM);
        cudaFuncSetAttribute(k_scan, cudaFuncAttributeMaxDynamicSharedMemorySize, SCAN_SMEM);
        attr_done = 1;
    }

    k_gemm <<<256, 256, GEMM_SMEM>>>(inp, W, bias, alpha, bl, ba);
    k_scan <<<56, 64, SCAN_SMEM>>>(bl, ba);               // 56 blocks x 32 units
    k_align<<<1, 64>>>();
    k_out  <<<384, 256>>>((float*)d_out);                 // b-pair float2 IO
}